// round 10
// baseline (speedup 1.0000x reference)
#include <cuda_runtime.h>
#include <cuda_bf16.h>
#include <math.h>
#include <stdint.h>

// Problem constants: B=8, T=4096, H=8, D=64, CK=512, K=8, C=64, MODES=32, L=2

#define DEVBUF __device__ __align__(256)
DEVBUF float g_d0  [8ull*2048*512];
DEVBUF float g_s0  [8ull*2048*512];
DEVBUF float g_d1  [8ull*1024*512];
DEVBUF float g_s1  [8ull*1024*512];
DEVBUF float g_US0 [16ull*2048*512];   // [0..8) = Ud0 batches, [8..16) = Us0
DEVBUF float g_US1 [16ull*1024*512];   // [0..8) = Ud1, [8..16) = Us1
DEVBUF float g_rec1[8ull*2048*512];
DEVBUF float g_rec0[8ull*4096*512];
DEVBUF float g_zf_part[8ull*32*512*64];
DEVBUF float g_zf     [32ull*512*64];
DEVBUF float g_mixp[4ull*32*512*64];   // modemix partials (i-split 4), [slot][o][m]
DEVBUF float g_mix [32ull*512*64];     // [slot][o(512)][m(64)]
DEVBUF float g_bF2048[2048*64];
DEVBUF float g_bI2048[2048*64];        // tf32-prerounded
DEVBUF float g_bF1024[1024*64];
DEVBUF float g_bI1024[1024*64];        // tf32-prerounded
DEVBUF float g_bt32[512ull*512];

// ===========================================================================
// Helpers (sm_80-baseline PTX: mma.sync tf32 / ldmatrix / cp.async)
// ===========================================================================
__device__ __forceinline__ uint32_t smem_u32(const void* p) {
    uint32_t a;
    asm("{ .reg .u64 t; cvta.to.shared.u64 t, %1; cvt.u32.u64 %0, t; }" : "=r"(a) : "l"(p));
    return a;
}
__device__ __forceinline__ void cp16(uint32_t smaddr, const void* g) {
    asm volatile("cp.async.cg.shared.global [%0], [%1], 16;" :: "r"(smaddr), "l"(g));
}
#define CP_COMMIT() asm volatile("cp.async.commit_group;" ::: "memory")
#define CP_WAIT2()  asm volatile("cp.async.wait_group 2;" ::: "memory")

__device__ __forceinline__ void ldsm4(uint32_t* r, uint32_t a) {
    asm volatile("ldmatrix.sync.aligned.m8n8.x4.shared.b16 {%0,%1,%2,%3}, [%4];"
        : "=r"(r[0]), "=r"(r[1]), "=r"(r[2]), "=r"(r[3]) : "r"(a));
}
__device__ __forceinline__ void ldsm2(uint32_t* r, uint32_t a) {
    asm volatile("ldmatrix.sync.aligned.m8n8.x2.shared.b16 {%0,%1}, [%2];"
        : "=r"(r[0]), "=r"(r[1]) : "r"(a));
}
__device__ __forceinline__ void mma_tf32(float* c, const uint32_t* a, const uint32_t* b) {
    asm volatile("mma.sync.aligned.m16n8k8.row.col.f32.tf32.tf32.f32 "
        "{%0,%1,%2,%3}, {%4,%5,%6,%7}, {%8,%9}, {%0,%1,%2,%3};"
        : "+f"(c[0]), "+f"(c[1]), "+f"(c[2]), "+f"(c[3])
        : "r"(a[0]), "r"(a[1]), "r"(a[2]), "r"(a[3]), "r"(b[0]), "r"(b[1]));
}
__device__ __forceinline__ uint32_t cvt_tf32(uint32_t u) {
    uint32_t o;
    float f = __uint_as_float(u);
    asm("cvt.rna.tf32.f32 %0, %1;" : "=r"(o) : "f"(f));
    return o;
}

// ===========================================================================
// lin_in GEMM with FUSED two-level encode epilogue.
// C-tile (128x128) staged in smem; writes d0,s0,d1,s1 directly; z never hits
// DRAM. Dynamic smem (floats): [0,16896) stage 128x132 ; [16896,25344) s0
// stash 64x132 ; [25344,25472) ec_d ; [25472,25600) ec_s.  102400 bytes.
// ===========================================================================
#define ENC_SMEM 102400

__global__ __launch_bounds__(256, 2) void gemm_tf32_enc(
    const float* __restrict__ A, const float* __restrict__ Bt,
    const float* __restrict__ bias,
    const float* __restrict__ ec_d, const float* __restrict__ ec_s,
    float* __restrict__ d0o, float* __restrict__ s0o,
    float* __restrict__ d1o, float* __restrict__ s1o)
{
    extern __shared__ __align__(1024) float dsm[];
    const int tid  = threadIdx.x;
    const int wid  = tid >> 5;
    const int lane = tid & 31;
    const int m0 = blockIdx.y * 128;
    const int n0 = blockIdx.x * 128;
    const int wm = (wid >> 1) * 32;
    const int wn = (wid & 1) * 64;

    // encode matrices -> tail of dynamic smem (survives mainloop)
    if (tid < 128) dsm[25344 + tid] = ec_d[tid];
    else           dsm[25344 + tid] = ec_s[tid - 128];

    const uint32_t sbase = smem_u32(dsm);
    const uint32_t sA0 = sbase;
    const uint32_t sB0 = sbase + 24576;

    const int r0 = (tid + 0)   >> 2, c0 = (tid + 0)   & 3;
    const int r1 = (tid + 256) >> 2, c1 = (tid + 256) & 3;
    const uint32_t so0 = (uint32_t)(r0 * 64 + ((c0 ^ ((r0 >> 1) & 3)) * 16));
    const uint32_t so1 = (uint32_t)(r1 * 64 + ((c1 ^ ((r1 >> 1) & 3)) * 16));

    auto load_chunk = [&](int it, int s) {
        const int kb = it * 16;
        cp16(sA0 + s * 8192 + so0, A + (size_t)(m0 + r0) * 512 + kb + c0 * 4);
        cp16(sA0 + s * 8192 + so1, A + (size_t)(m0 + r1) * 512 + kb + c1 * 4);
        cp16(sB0 + s * 8192 + so0, Bt + (size_t)(n0 + r0) * 512 + kb + c0 * 4);
        cp16(sB0 + s * 8192 + so1, Bt + (size_t)(n0 + r1) * 512 + kb + c1 * 4);
        CP_COMMIT();
    };

    float acc[2][8][4];
#pragma unroll
    for (int i = 0; i < 2; i++)
#pragma unroll
        for (int j = 0; j < 8; j++)
#pragma unroll
            for (int k = 0; k < 4; k++) acc[i][j][k] = 0.f;

    const int la = lane & 15;
    const int ka = lane >> 4;
    const int lb = lane & 7;
    const int kb8 = (lane >> 3) & 1;

    load_chunk(0, 0);
    load_chunk(1, 1);

    const int NC = 32;
    for (int it = 0; it < NC; it++) {
        const int s = it % 3;
        if (it + 2 < NC) load_chunk(it + 2, (it + 2) % 3);
        else CP_COMMIT();
        CP_WAIT2();
        __syncthreads();

#pragma unroll
        for (int k8 = 0; k8 < 2; k8++) {
            uint32_t afr[2][4];
#pragma unroll
            for (int tm = 0; tm < 2; tm++) {
                int row = wm + tm * 16 + la;
                int k4 = k8 * 2 + ka;
                uint32_t addr = sA0 + s * 8192 + (uint32_t)(row * 64 + ((k4 ^ ((row >> 1) & 3)) * 16));
                ldsm4(afr[tm], addr);
#pragma unroll
                for (int q = 0; q < 4; q++) afr[tm][q] = cvt_tf32(afr[tm][q]);
            }
            uint32_t bfr[8][2];
#pragma unroll
            for (int n8 = 0; n8 < 8; n8++) {
                int row = wn + n8 * 8 + lb;
                int k4 = k8 * 2 + kb8;
                uint32_t addr = sB0 + s * 8192 + (uint32_t)(row * 64 + ((k4 ^ ((row >> 1) & 3)) * 16));
                ldsm2(bfr[n8], addr);
            }
#pragma unroll
            for (int tm = 0; tm < 2; tm++)
#pragma unroll
                for (int n8 = 0; n8 < 8; n8++)
                    mma_tf32(acc[tm][n8], afr[tm], bfr[n8]);
        }
        __syncthreads();
    }

    // ---- stage C tile (with bias) ----
    const int er = lane >> 2;
    const int ec = (lane & 3) * 2;
    float* st = dsm;
#pragma unroll
    for (int tm = 0; tm < 2; tm++) {
        int r = wm + tm * 16 + er;
#pragma unroll
        for (int n8 = 0; n8 < 8; n8++) {
            int cn = wn + n8 * 8 + ec;
            float b0 = bias[n0 + cn], b1 = bias[n0 + cn + 1];
            *(float2*)&st[r * 132 + cn]       = make_float2(acc[tm][n8][0] + b0, acc[tm][n8][1] + b1);
            *(float2*)&st[(r + 8) * 132 + cn] = make_float2(acc[tm][n8][2] + b0, acc[tm][n8][3] + b1);
        }
    }
    __syncthreads();

    const float* ed = dsm + 25344;
    const float* es = dsm + 25472;
    float* s0s = dsm + 16896;
    const int b = m0 >> 12;
    const int tb0 = (m0 & 4095) >> 1;
    const int tb1 = (m0 & 4095) >> 2;
    const int cg0 = n0 >> 3;

    // ---- encode level 0: 64 pairs x 16 channels ----
#pragma unroll
    for (int itk = 0; itk < 4; itk++) {
        int task = tid + itk * 256;
        int cl = task & 15;
        int p  = task >> 4;         // 0..63
        const float* pr0 = &st[(2 * p) * 132 + cl * 8];
        const float* pr1 = &st[(2 * p + 1) * 132 + cl * 8];
        float4 e0 = *(const float4*)(pr0 + 0), e1 = *(const float4*)(pr0 + 4);
        float4 o0 = *(const float4*)(pr1 + 0), o1 = *(const float4*)(pr1 + 4);
        float xa[16] = {e0.x,e0.y,e0.z,e0.w,e1.x,e1.y,e1.z,e1.w,
                        o0.x,o0.y,o0.z,o0.w,o1.x,o1.y,o1.z,o1.w};
        float d[8] = {0,0,0,0,0,0,0,0}, s[8] = {0,0,0,0,0,0,0,0};
#pragma unroll
        for (int j = 0; j < 16; j++)
#pragma unroll
            for (int k = 0; k < 8; k++) {
                d[k] = fmaf(xa[j], ed[j * 8 + k], d[k]);
                s[k] = fmaf(xa[j], es[j * 8 + k], s[k]);
            }
        size_t o = (((size_t)b * 2048 + tb0 + p) * 64 + (cg0 + cl)) * 8;
        *(float4*)&d0o[o]     = make_float4(d[0], d[1], d[2], d[3]);
        *(float4*)&d0o[o + 4] = make_float4(d[4], d[5], d[6], d[7]);
        *(float4*)&s0o[o]     = make_float4(s[0], s[1], s[2], s[3]);
        *(float4*)&s0o[o + 4] = make_float4(s[4], s[5], s[6], s[7]);
        *(float4*)&s0s[p * 132 + cl * 8]     = make_float4(s[0], s[1], s[2], s[3]);
        *(float4*)&s0s[p * 132 + cl * 8 + 4] = make_float4(s[4], s[5], s[6], s[7]);
    }
    __syncthreads();

    // ---- encode level 1: 32 pairs x 16 channels ----
#pragma unroll
    for (int itk = 0; itk < 2; itk++) {
        int task = tid + itk * 256;
        int cl = task & 15;
        int p  = task >> 4;         // 0..31
        const float* pr0 = &s0s[(2 * p) * 132 + cl * 8];
        const float* pr1 = &s0s[(2 * p + 1) * 132 + cl * 8];
        float4 e0 = *(const float4*)(pr0 + 0), e1 = *(const float4*)(pr0 + 4);
        float4 o0 = *(const float4*)(pr1 + 0), o1 = *(const float4*)(pr1 + 4);
        float xa[16] = {e0.x,e0.y,e0.z,e0.w,e1.x,e1.y,e1.z,e1.w,
                        o0.x,o0.y,o0.z,o0.w,o1.x,o1.y,o1.z,o1.w};
        float d[8] = {0,0,0,0,0,0,0,0}, s[8] = {0,0,0,0,0,0,0,0};
#pragma unroll
        for (int j = 0; j < 16; j++)
#pragma unroll
            for (int k = 0; k < 8; k++) {
                d[k] = fmaf(xa[j], ed[j * 8 + k], d[k]);
                s[k] = fmaf(xa[j], es[j * 8 + k], s[k]);
            }
        size_t o = (((size_t)b * 1024 + tb1 + p) * 64 + (cg0 + cl)) * 8;
        *(float4*)&d1o[o]     = make_float4(d[0], d[1], d[2], d[3]);
        *(float4*)&d1o[o + 4] = make_float4(d[4], d[5], d[6], d[7]);
        *(float4*)&s1o[o]     = make_float4(s[0], s[1], s[2], s[3]);
        *(float4*)&s1o[o + 4] = make_float4(s[4], s[5], s[6], s[7]);
    }
}

// ===========================================================================
// tf32 mma GEMM (plain, for lin_out)
// ===========================================================================
__global__ __launch_bounds__(256, 2) void gemm_tf32(
    const float* __restrict__ A, const float* __restrict__ Bt,
    const float* __restrict__ bias, float* __restrict__ C)
{
    __shared__ __align__(1024) float sA[3][128 * 16];
    __shared__ __align__(1024) float sB[3][128 * 16];

    const int tid  = threadIdx.x;
    const int wid  = tid >> 5;
    const int lane = tid & 31;
    const int m0 = blockIdx.y * 128;
    const int n0 = blockIdx.x * 128;
    const int wm = (wid >> 1) * 32;
    const int wn = (wid & 1) * 64;

    const uint32_t sA0 = smem_u32(sA);
    const uint32_t sB0 = smem_u32(sB);

    const int r0 = (tid + 0)   >> 2, c0 = (tid + 0)   & 3;
    const int r1 = (tid + 256) >> 2, c1 = (tid + 256) & 3;
    const uint32_t so0 = (uint32_t)(r0 * 64 + ((c0 ^ ((r0 >> 1) & 3)) * 16));
    const uint32_t so1 = (uint32_t)(r1 * 64 + ((c1 ^ ((r1 >> 1) & 3)) * 16));

    auto load_chunk = [&](int it, int s) {
        const int kb = it * 16;
        cp16(sA0 + s * 8192 + so0, A + (size_t)(m0 + r0) * 512 + kb + c0 * 4);
        cp16(sA0 + s * 8192 + so1, A + (size_t)(m0 + r1) * 512 + kb + c1 * 4);
        cp16(sB0 + s * 8192 + so0, Bt + (size_t)(n0 + r0) * 512 + kb + c0 * 4);
        cp16(sB0 + s * 8192 + so1, Bt + (size_t)(n0 + r1) * 512 + kb + c1 * 4);
        CP_COMMIT();
    };

    float acc[2][8][4];
#pragma unroll
    for (int i = 0; i < 2; i++)
#pragma unroll
        for (int j = 0; j < 8; j++)
#pragma unroll
            for (int k = 0; k < 4; k++) acc[i][j][k] = 0.f;

    const int la = lane & 15;
    const int ka = lane >> 4;
    const int lb = lane & 7;
    const int kb8 = (lane >> 3) & 1;

    load_chunk(0, 0);
    load_chunk(1, 1);

    const int NC = 32;
    for (int it = 0; it < NC; it++) {
        const int s = it % 3;
        if (it + 2 < NC) load_chunk(it + 2, (it + 2) % 3);
        else CP_COMMIT();
        CP_WAIT2();
        __syncthreads();

#pragma unroll
        for (int k8 = 0; k8 < 2; k8++) {
            uint32_t afr[2][4];
#pragma unroll
            for (int tm = 0; tm < 2; tm++) {
                int row = wm + tm * 16 + la;
                int k4 = k8 * 2 + ka;
                uint32_t addr = sA0 + s * 8192 + (uint32_t)(row * 64 + ((k4 ^ ((row >> 1) & 3)) * 16));
                ldsm4(afr[tm], addr);
#pragma unroll
                for (int q = 0; q < 4; q++) afr[tm][q] = cvt_tf32(afr[tm][q]);
            }
            uint32_t bfr[8][2];
#pragma unroll
            for (int n8 = 0; n8 < 8; n8++) {
                int row = wn + n8 * 8 + lb;
                int k4 = k8 * 2 + kb8;
                uint32_t addr = sB0 + s * 8192 + (uint32_t)(row * 64 + ((k4 ^ ((row >> 1) & 3)) * 16));
                ldsm2(bfr[n8], addr);
            }
#pragma unroll
            for (int tm = 0; tm < 2; tm++)
#pragma unroll
                for (int n8 = 0; n8 < 8; n8++)
                    mma_tf32(acc[tm][n8], afr[tm], bfr[n8]);
        }
        __syncthreads();
    }

    const int er = lane >> 2;
    const int ec = (lane & 3) * 2;
#pragma unroll
    for (int tm = 0; tm < 2; tm++) {
        const int m = m0 + wm + tm * 16 + er;
#pragma unroll
        for (int n8 = 0; n8 < 8; n8++) {
            const int n = n0 + wn + n8 * 8 + ec;
            const float b0 = bias[n], b1 = bias[n + 1];
            float2 v0 = make_float2(acc[tm][n8][0] + b0, acc[tm][n8][1] + b1);
            float2 v1 = make_float2(acc[tm][n8][2] + b0, acc[tm][n8][3] + b1);
            *(float2*)&C[(size_t)m * 512 + n]       = v0;
            *(float2*)&C[(size_t)(m + 8) * 512 + n] = v1;
        }
    }
}

__global__ void wgt_tf32(const float* __restrict__ W, float* __restrict__ Bt) {
    __shared__ float t[32][33];
    const int n0 = blockIdx.x * 32, k0 = blockIdx.y * 32;
    for (int i = threadIdx.y; i < 32; i += 8)
        t[i][threadIdx.x] = W[(size_t)(k0 + i) * 512 + n0 + threadIdx.x];
    __syncthreads();
    for (int i = threadIdx.y; i < 32; i += 8) {
        uint32_t v = cvt_tf32(__float_as_uint(t[threadIdx.x][i]));
        Bt[(size_t)(n0 + i) * 512 + k0 + threadIdx.x] = __uint_as_float(v);
    }
}

// ===========================================================================
// Inverse-DFT via tf32 mma: C[z][t][i] = bI[t][m] @ mixT[z][i][m]
// ===========================================================================
__global__ __launch_bounds__(256, 2) void invdft_tf32(
    const float* __restrict__ Abi, const float* __restrict__ Bm,
    float* __restrict__ C, int n2)
{
    __shared__ __align__(1024) float sA[3][128 * 16];
    __shared__ __align__(1024) float sB[3][128 * 16];

    const int tid  = threadIdx.x;
    const int wid  = tid >> 5;
    const int lane = tid & 31;
    const int m0 = blockIdx.y * 128;
    const int n0 = blockIdx.x * 128;
    const int z  = blockIdx.z;
    Bm += (size_t)z * 512 * 64;
    C  += (size_t)z * n2 * 512;
    const int wm = (wid >> 1) * 32;
    const int wn = (wid & 1) * 64;

    const uint32_t sA0 = smem_u32(sA);
    const uint32_t sB0 = smem_u32(sB);

    const int r0 = tid >> 2, c0 = tid & 3;
    const int r1 = r0 + 64;
    const uint32_t so0 = (uint32_t)(r0 * 64 + ((c0 ^ ((r0 >> 1) & 3)) * 16));
    const uint32_t so1 = (uint32_t)(r1 * 64 + ((c0 ^ ((r1 >> 1) & 3)) * 16));

    auto load_chunk = [&](int it, int s) {
        const int kb = it * 16;
        cp16(sA0 + s * 8192 + so0, Abi + (size_t)(m0 + r0) * 64 + kb + c0 * 4);
        cp16(sA0 + s * 8192 + so1, Abi + (size_t)(m0 + r1) * 64 + kb + c0 * 4);
        cp16(sB0 + s * 8192 + so0, Bm + (size_t)(n0 + r0) * 64 + kb + c0 * 4);
        cp16(sB0 + s * 8192 + so1, Bm + (size_t)(n0 + r1) * 64 + kb + c0 * 4);
        CP_COMMIT();
    };

    float acc[2][8][4];
#pragma unroll
    for (int i = 0; i < 2; i++)
#pragma unroll
        for (int j = 0; j < 8; j++)
#pragma unroll
            for (int k = 0; k < 4; k++) acc[i][j][k] = 0.f;

    const int la = lane & 15;
    const int ka = lane >> 4;
    const int b_r = wn + (lane & 7) + ((lane & 16) ? 8 : 0);
    const int b_u = (lane >> 3) & 1;

    load_chunk(0, 0);
    load_chunk(1, 1);

    const int NC = 4;
    for (int it = 0; it < NC; it++) {
        const int s = it % 3;
        if (it + 2 < NC) load_chunk(it + 2, (it + 2) % 3);
        else CP_COMMIT();
        CP_WAIT2();
        __syncthreads();

#pragma unroll
        for (int k8 = 0; k8 < 2; k8++) {
            uint32_t afr[2][4];
#pragma unroll
            for (int tm = 0; tm < 2; tm++) {
                int row = wm + tm * 16 + la;
                int k4 = k8 * 2 + ka;
                uint32_t addr = sA0 + s * 8192 + (uint32_t)(row * 64 + ((k4 ^ ((row >> 1) & 3)) * 16));
                ldsm4(afr[tm], addr);
            }
            uint32_t bfr[4][4];
#pragma unroll
            for (int p = 0; p < 4; p++) {
                int row = b_r + p * 16;
                int k4 = k8 * 2 + b_u;
                uint32_t addr = sB0 + s * 8192 + (uint32_t)(row * 64 + ((k4 ^ ((row >> 1) & 3)) * 16));
                ldsm4(bfr[p], addr);
#pragma unroll
                for (int q = 0; q < 4; q++) bfr[p][q] = cvt_tf32(bfr[p][q]);
            }
#pragma unroll
            for (int tm = 0; tm < 2; tm++)
#pragma unroll
                for (int p = 0; p < 4; p++) {
                    mma_tf32(acc[tm][p * 2 + 0], afr[tm], &bfr[p][0]);
                    mma_tf32(acc[tm][p * 2 + 1], afr[tm], &bfr[p][2]);
                }
        }
        __syncthreads();
    }

    const int er = lane >> 2;
    const int ec = (lane & 3) * 2;
#pragma unroll
    for (int tm = 0; tm < 2; tm++) {
        const int m = m0 + wm + tm * 16 + er;
#pragma unroll
        for (int n8 = 0; n8 < 8; n8++) {
            const int n = n0 + wn + n8 * 8 + ec;
            *(float2*)&C[(size_t)m * 512 + n]       = make_float2(acc[tm][n8][0], acc[tm][n8][1]);
            *(float2*)&C[(size_t)(m + 8) * 512 + n] = make_float2(acc[tm][n8][2], acc[tm][n8][3]);
        }
    }
}

// ===========================================================================
// Basis tables (bI pre-rounded to tf32)
// ===========================================================================
__device__ __forceinline__ void fill_tables(float* bF, float* bI, int t, int m, int n) {
    int x = (m < 32) ? m : (m - 32);
    long r = ((long)t * (long)x) % (long)n;
    double ang = 6.283185307179586476925286766559 * (double)r / (double)n;
    double c = cos(ang), s = sin(ang);
    bF[t*64 + m] = (m < 32) ? (float)c : (float)s;
    float vi;
    if (m == 0)          vi = 1.0f / (float)n;
    else if (m < 32)     vi = (float)(2.0 * c / (double)n);
    else if (m == 32)    vi = 0.0f;
    else                 vi = (float)(-2.0 * s / (double)n);
    bI[t*64 + m] = __uint_as_float(cvt_tf32(__float_as_uint(vi)));
}

__global__ __launch_bounds__(256) void basis_kernel() {
    int idx = blockIdx.x * 256 + threadIdx.x;
    if (idx < 2048*64) {
        int t = idx >> 6, m = idx & 63;
        fill_tables(g_bF2048, g_bI2048, t, m, 2048);
    }
    if (idx < 1024*64) {
        int t = idx >> 6, m = idx & 63;
        fill_tables(g_bF1024, g_bI1024, t, m, 1024);
    }
}

// ===========================================================================
// Forward truncated DFT, BOTH levels in one launch (grid.z = 32)
// g<16: lev0 (n=2048,kc=256), else lev1 (n=1024,kc=128). slot = g.
// ===========================================================================
__global__ __launch_bounds__(256) void dftfwd_kernel(
    const float* __restrict__ zd0, const float* __restrict__ zs0,
    const float* __restrict__ zd1, const float* __restrict__ zs1,
    const float* __restrict__ bF0, const float* __restrict__ bF1,
    float* __restrict__ out_part)
{
    __shared__ float As[16][128];
    __shared__ float Bs[16][64];
    const int tid = threadIdx.x;
    const int g = blockIdx.z;
    const float* z;
    const float* bF;
    int n, kchunk;
    if (g < 16) { z = (g < 8) ? zd0 : zs0; bF = bF0; n = 2048; kchunk = 256; }
    else        { z = (g < 24) ? zd1 : zs1; bF = bF1; n = 1024; kchunk = 128; }
    z += (size_t)(g & 7) * n * 512;
    const int i0 = blockIdx.x * 128;
    const int tbase = blockIdx.y * kchunk;

    const int tx = tid & 15;
    const int ty = tid >> 4;

    float acc[8][4];
#pragma unroll
    for (int i = 0; i < 8; i++)
#pragma unroll
        for (int j = 0; j < 4; j++) acc[i][j] = 0.f;

    for (int tc = 0; tc < kchunk; tc += 16) {
#pragma unroll
        for (int p = 0; p < 2; p++) {
            int tr = (tid >> 5) + p * 8;
            int ic = (tid & 31) * 4;
            *(float4*)&As[tr][ic] = *(const float4*)&z[(size_t)(tbase + tc + tr) * 512 + i0 + ic];
        }
        {
            int tr = tid >> 4;
            int mc = (tid & 15) * 4;
            *(float4*)&Bs[tr][mc] = *(const float4*)&bF[(size_t)(tbase + tc + tr) * 64 + mc];
        }
        __syncthreads();
#pragma unroll
        for (int kk = 0; kk < 16; kk++) {
            float4 a0 = *(const float4*)&As[kk][ty * 8 + 0];
            float4 a1 = *(const float4*)&As[kk][ty * 8 + 4];
            float4 bv = *(const float4*)&Bs[kk][tx * 4];
            float av[8] = {a0.x,a0.y,a0.z,a0.w,a1.x,a1.y,a1.z,a1.w};
            float bb[4] = {bv.x,bv.y,bv.z,bv.w};
#pragma unroll
            for (int i = 0; i < 8; i++)
#pragma unroll
                for (int j = 0; j < 4; j++)
                    acc[i][j] = fmaf(av[i], bb[j], acc[i][j]);
        }
        __syncthreads();
    }
#pragma unroll
    for (int i = 0; i < 8; i++) {
        size_t base = (((size_t)blockIdx.y * 32 + g) * 512 + (i0 + ty * 8 + i)) * 64 + tx * 4;
        float4 o = make_float4(acc[i][0], acc[i][1], acc[i][2], acc[i][3]);
        *(float4*)&out_part[base] = o;
    }
}

__global__ __launch_bounds__(256) void reduce_parts(
    const float* __restrict__ part, float* __restrict__ out, int count, int nparts)
{
    int e = blockIdx.x * 256 + threadIdx.x;
    if (e >= count) return;
    float s = 0.f;
    for (int p = 0; p < nparts; p++) s += part[(size_t)p * count + e];
    out[e] = s;
}

// ===========================================================================
// Mode mixing, both levels, i-split 4. Output layout [slot][o][m] (m contig).
// ===========================================================================
__global__ __launch_bounds__(256) void modemix_kernel(
    const float* __restrict__ zf,
    const float* __restrict__ waR, const float* __restrict__ waI,
    const float* __restrict__ wbR, const float* __restrict__ wbI,
    const float* __restrict__ wcR, const float* __restrict__ wcI,
    float* __restrict__ out_part)
{
    __shared__ float zdS[2][8][8][64];
    __shared__ float zsS[2][8][8][64];
    const int x = threadIdx.x & 31;
    const int q = threadIdx.x >> 5;
    const int o = blockIdx.x * 8 + q;
    const int i0 = blockIdx.y * 128;

    float uR[16], uI[16], sR[16], sI[16];
#pragma unroll
    for (int b = 0; b < 16; b++) { uR[b]=0.f; uI[b]=0.f; sR[b]=0.f; sI[b]=0.f; }

    for (int ic = 0; ic < 128; ic += 8) {
        __syncthreads();
        for (int e = threadIdx.x; e < 8192; e += 256) {
            int lev = e >> 12, r = e & 4095;
            int b = r >> 9, rr = r & 511, ii = rr >> 6, xx = rr & 63;
            size_t gidx = ((size_t)b * 512 + (i0 + ic + ii)) * 64 + xx;
            size_t lbase = (size_t)lev * 16 * 512 * 64;
            zdS[lev][b][ii][xx] = zf[lbase + gidx];
            zsS[lev][b][ii][xx] = zf[lbase + 8ull * 512 * 64 + gidx];
        }
        __syncthreads();
#pragma unroll 2
        for (int ii = 0; ii < 8; ii++) {
            int i = i0 + ic + ii;
            size_t wbase = ((size_t)i * 512 + o) * 32 + x;
            float war = waR[wbase], wai = waI[wbase];
            float wbr = wbR[wbase], wbi = wbI[wbase];
            float wcr = wcR[wbase], wci = wcI[wbase];
#pragma unroll
            for (int lev = 0; lev < 2; lev++)
#pragma unroll
            for (int b = 0; b < 8; b++) {
                int bb = lev * 8 + b;
                float zr = zdS[lev][b][ii][x];
                float zi = -zdS[lev][b][ii][32 + x];
                float sr = zsS[lev][b][ii][x];
                float si = -zsS[lev][b][ii][32 + x];
                uR[bb] = fmaf(zr, war, uR[bb]); uR[bb] = fmaf(-zi, wai, uR[bb]);
                uR[bb] = fmaf(sr, wbr, uR[bb]); uR[bb] = fmaf(-si, wbi, uR[bb]);
                uI[bb] = fmaf(zr, wai, uI[bb]); uI[bb] = fmaf(zi, war, uI[bb]);
                uI[bb] = fmaf(sr, wbi, uI[bb]); uI[bb] = fmaf(si, wbr, uI[bb]);
                sR[bb] = fmaf(zr, wcr, sR[bb]); sR[bb] = fmaf(-zi, wci, sR[bb]);
                sI[bb] = fmaf(zr, wci, sI[bb]); sI[bb] = fmaf(zi, wcr, sI[bb]);
            }
        }
    }
#pragma unroll
    for (int bb = 0; bb < 16; bb++) {
        int lev = bb >> 3, b = bb & 7;
        size_t slotU = (size_t)blockIdx.y * 32 + lev * 16 + b;
        size_t slotS = slotU + 8;
        out_part[(slotU * 512 + o) * 64 + x]      = uR[bb];
        out_part[(slotU * 512 + o) * 64 + 32 + x] = uI[bb];
        out_part[(slotS * 512 + o) * 64 + x]      = sR[bb];
        out_part[(slotS * 512 + o) * 64 + 32 + x] = sI[bb];
    }
}

// ===========================================================================
// Recon with fused t0 (level 1), 2 channels/thread
// ===========================================================================
__global__ __launch_bounds__(256) void recon_t0_kernel(
    const float* __restrict__ cur, const float* __restrict__ us,
    const float* __restrict__ ud, const float* __restrict__ rc_e,
    const float* __restrict__ rc_o, const float* __restrict__ t0w,
    const float* __restrict__ t0b, float* __restrict__ out, int n2)
{
    __shared__ float re[128], ro[128], w[64], bb[8];
    if (threadIdx.x < 128) { re[threadIdx.x] = rc_e[threadIdx.x]; ro[threadIdx.x] = rc_o[threadIdx.x]; }
    if (threadIdx.x < 64)  w[threadIdx.x] = t0w[threadIdx.x];
    if (threadIdx.x >= 64 && threadIdx.x < 72) bb[threadIdx.x - 64] = t0b[threadIdx.x - 64];
    __syncthreads();
    int idx = blockIdx.x * 256 + threadIdx.x;
    int total = 8 * n2 * 32;
    if (idx >= total) return;
    int cp = idx & 31;
    int bt = idx >> 5;

    float4 vc[2][2], vu[2][2], vd[2][2];
#pragma unroll
    for (int cc = 0; cc < 2; cc++) {
        size_t base = ((size_t)bt * 64 + cp * 2 + cc) * 8;
        vc[cc][0] = *(const float4*)(cur + base); vc[cc][1] = *(const float4*)(cur + base + 4);
        vu[cc][0] = *(const float4*)(us + base);  vu[cc][1] = *(const float4*)(us + base + 4);
        vd[cc][0] = *(const float4*)(ud + base);  vd[cc][1] = *(const float4*)(ud + base + 4);
    }
#pragma unroll
    for (int cc = 0; cc < 2; cc++) {
        int c = cp * 2 + cc;
        float sv[8] = {vc[cc][0].x,vc[cc][0].y,vc[cc][0].z,vc[cc][0].w,
                       vc[cc][1].x,vc[cc][1].y,vc[cc][1].z,vc[cc][1].w};
        float uu[8] = {vu[cc][0].x,vu[cc][0].y,vu[cc][0].z,vu[cc][0].w,
                       vu[cc][1].x,vu[cc][1].y,vu[cc][1].z,vu[cc][1].w};
        float v[16];
        v[8]=vd[cc][0].x; v[9]=vd[cc][0].y; v[10]=vd[cc][0].z; v[11]=vd[cc][0].w;
        v[12]=vd[cc][1].x; v[13]=vd[cc][1].y; v[14]=vd[cc][1].z; v[15]=vd[cc][1].w;
#pragma unroll
        for (int k = 0; k < 8; k++) {
            float t = bb[k];
#pragma unroll
            for (int j = 0; j < 8; j++) t = fmaf(sv[j], w[j * 8 + k], t);
            v[k] = t + uu[k];
        }
        float xe[8] = {0,0,0,0,0,0,0,0}, xo[8] = {0,0,0,0,0,0,0,0};
#pragma unroll
        for (int j = 0; j < 16; j++)
#pragma unroll
            for (int k = 0; k < 8; k++) {
                xe[k] = fmaf(v[j], re[j * 8 + k], xe[k]);
                xo[k] = fmaf(v[j], ro[j * 8 + k], xo[k]);
            }
        float* pe = out + ((size_t)(128 * bt + c)) * 8;
        *(float4*)(pe + 0)   = make_float4(xe[0], xe[1], xe[2], xe[3]);
        *(float4*)(pe + 4)   = make_float4(xe[4], xe[5], xe[6], xe[7]);
        *(float4*)(pe + 512) = make_float4(xo[0], xo[1], xo[2], xo[3]);
        *(float4*)(pe + 516) = make_float4(xo[4], xo[5], xo[6], xo[7]);
    }
}

// Recon (level 0), 2 channels/thread
__global__ __launch_bounds__(256) void recon_kernel(
    const float* __restrict__ cur, const float* __restrict__ us,
    const float* __restrict__ ud, const float* __restrict__ rc_e,
    const float* __restrict__ rc_o, float* __restrict__ out, int n2)
{
    __shared__ float re[128], ro[128];
    if (threadIdx.x < 128) { re[threadIdx.x] = rc_e[threadIdx.x]; ro[threadIdx.x] = rc_o[threadIdx.x]; }
    __syncthreads();
    int idx = blockIdx.x * 256 + threadIdx.x;
    int total = 8 * n2 * 32;
    if (idx >= total) return;
    int cp = idx & 31;
    int bt = idx >> 5;

    float4 vc[2][2], vu[2][2], vd[2][2];
#pragma unroll
    for (int cc = 0; cc < 2; cc++) {
        size_t base = ((size_t)bt * 64 + cp * 2 + cc) * 8;
        vc[cc][0] = *(const float4*)(cur + base); vc[cc][1] = *(const float4*)(cur + base + 4);
        vu[cc][0] = *(const float4*)(us + base);  vu[cc][1] = *(const float4*)(us + base + 4);
        vd[cc][0] = *(const float4*)(ud + base);  vd[cc][1] = *(const float4*)(ud + base + 4);
    }
#pragma unroll
    for (int cc = 0; cc < 2; cc++) {
        int c = cp * 2 + cc;
        float v[16];
        v[0]=vc[cc][0].x+vu[cc][0].x; v[1]=vc[cc][0].y+vu[cc][0].y;
        v[2]=vc[cc][0].z+vu[cc][0].z; v[3]=vc[cc][0].w+vu[cc][0].w;
        v[4]=vc[cc][1].x+vu[cc][1].x; v[5]=vc[cc][1].y+vu[cc][1].y;
        v[6]=vc[cc][1].z+vu[cc][1].z; v[7]=vc[cc][1].w+vu[cc][1].w;
        v[8]=vd[cc][0].x; v[9]=vd[cc][0].y; v[10]=vd[cc][0].z; v[11]=vd[cc][0].w;
        v[12]=vd[cc][1].x; v[13]=vd[cc][1].y; v[14]=vd[cc][1].z; v[15]=vd[cc][1].w;
        float xe[8] = {0,0,0,0,0,0,0,0}, xo[8] = {0,0,0,0,0,0,0,0};
#pragma unroll
        for (int j = 0; j < 16; j++)
#pragma unroll
            for (int k = 0; k < 8; k++) {
                xe[k] = fmaf(v[j], re[j * 8 + k], xe[k]);
                xo[k] = fmaf(v[j], ro[j * 8 + k], xo[k]);
            }
        float* pe = out + ((size_t)(128 * bt + c)) * 8;
        *(float4*)(pe + 0)   = make_float4(xe[0], xe[1], xe[2], xe[3]);
        *(float4*)(pe + 4)   = make_float4(xe[4], xe[5], xe[6], xe[7]);
        *(float4*)(pe + 512) = make_float4(xo[0], xo[1], xo[2], xo[3]);
        *(float4*)(pe + 516) = make_float4(xo[4], xo[5], xo[6], xo[7]);
    }
}

// ===========================================================================
// Host orchestration
// ===========================================================================
#define SYM(p, s) do { void* _t; cudaGetSymbolAddress(&_t, s); p = (decltype(p))_t; } while (0)

extern "C" void kernel_launch(void* const* d_in, const int* in_sizes, int n_in,
                              void* d_out, int out_size)
{
    const float* x        = (const float*)d_in[0];
    const float* lin_in_w = (const float*)d_in[1];
    const float* lin_in_b = (const float*)d_in[2];
    const float* lin_out_w= (const float*)d_in[3];
    const float* lin_out_b= (const float*)d_in[4];
    const float* t0_w     = (const float*)d_in[5];
    const float* t0_b     = (const float*)d_in[6];
    const float* wA_re    = (const float*)d_in[7];
    const float* wA_im    = (const float*)d_in[8];
    const float* wB_re    = (const float*)d_in[9];
    const float* wB_im    = (const float*)d_in[10];
    const float* wC_re    = (const float*)d_in[11];
    const float* wC_im    = (const float*)d_in[12];
    const float* ec_s     = (const float*)d_in[13];
    const float* ec_d     = (const float*)d_in[14];
    const float* rc_e     = (const float*)d_in[15];
    const float* rc_o     = (const float*)d_in[16];

    float *pd0, *ps0, *pd1, *ps1, *pUS0, *pUS1;
    float *prec1, *prec0, *pzfp, *pzf, *pmixp, *pmix;
    float *pbF2, *pbI2, *pbF1, *pbI1, *pbt32;
    SYM(pd0, g_d0); SYM(ps0, g_s0);
    SYM(pd1, g_d1); SYM(ps1, g_s1);
    SYM(pUS0, g_US0); SYM(pUS1, g_US1);
    SYM(prec1, g_rec1); SYM(prec0, g_rec0);
    SYM(pzfp, g_zf_part); SYM(pzf, g_zf);
    SYM(pmixp, g_mixp); SYM(pmix, g_mix);
    SYM(pbF2, g_bF2048); SYM(pbI2, g_bI2048); SYM(pbF1, g_bF1024); SYM(pbI1, g_bI1024);
    SYM(pbt32, g_bt32);

    const int ZFCOUNT  = 32 * 512 * 64;
    const int MIXCOUNT = 32 * 512 * 64;

    cudaFuncSetAttribute(gemm_tf32_enc, cudaFuncAttributeMaxDynamicSharedMemorySize, ENC_SMEM);

    // 0) basis tables
    basis_kernel<<<512, 256>>>();

    // 1) lin_in via tf32 mma with fused 2-level encode (z never materialized)
    wgt_tf32<<<dim3(16, 16), dim3(32, 8)>>>(lin_in_w, pbt32);
    gemm_tf32_enc<<<dim3(4, 256), 256, ENC_SMEM>>>(x, pbt32, lin_in_b,
                                                   ec_d, ec_s, pd0, ps0, pd1, ps1);

    // 2) forward DFTs, both levels, one launch
    dftfwd_kernel<<<dim3(4, 8, 32), 256>>>(pd0, ps0, pd1, ps1, pbF2, pbF1, pzfp);
    reduce_parts<<<(ZFCOUNT + 255) / 256, 256>>>(pzfp, pzf, ZFCOUNT, 8);

    // 3) single modemix over both levels, i-split 4, [slot][o][m] output
    modemix_kernel<<<dim3(64, 4), 256>>>(pzf, wA_re, wA_im, wB_re, wB_im,
                                         wC_re, wC_im, pmixp);
    reduce_parts<<<(MIXCOUNT + 255) / 256, 256>>>(pmixp, pmix, MIXCOUNT, 4);

    // 4) inverse DFTs via tf32 mma (z-batched)
    invdft_tf32<<<dim3(4, 16, 16), 256>>>(pbI2, pmix, pUS0, 2048);
    invdft_tf32<<<dim3(4, 8, 16), 256>>>(pbI1, pmix + 16ull * 512 * 64, pUS1, 1024);

    // 5) reconstruction (t0 fused into level-1 recon)
    recon_t0_kernel<<<(8 * 1024 * 32) / 256, 256>>>(
        ps1, pUS1 + 8ull * 1024 * 512, pUS1, rc_e, rc_o, t0_w, t0_b, prec1, 1024);
    recon_kernel<<<(8 * 2048 * 32) / 256, 256>>>(
        prec1, pUS0 + 8ull * 2048 * 512, pUS0, rc_e, rc_o, prec0, 2048);

    // 6) lin_out via tf32 mma -> d_out
    wgt_tf32<<<dim3(16, 16), dim3(32, 8)>>>(lin_out_w, pbt32);
    gemm_tf32<<<dim3(4, 256), 256>>>(prec0, pbt32, lin_out_b, (float*)d_out);

    (void)in_sizes; (void)n_in; (void)out_size;
}

// round 11
// speedup vs baseline: 1.0444x; 1.0444x over previous
#include <cuda_runtime.h>
#include <cuda_bf16.h>
#include <math.h>
#include <stdint.h>

// Problem constants: B=8, T=4096, H=8, D=64, CK=512, K=8, C=64, MODES=32, L=2

#define DEVBUF __device__ __align__(256)
DEVBUF float g_z   [8ull*4096*512];
DEVBUF float g_d0  [8ull*2048*512];
DEVBUF float g_s0  [8ull*2048*512];
DEVBUF float g_d1  [8ull*1024*512];
DEVBUF float g_s1  [8ull*1024*512];
DEVBUF float g_US0 [16ull*2048*512];   // [0..8) = Ud0 batches, [8..16) = Us0
DEVBUF float g_US1 [16ull*1024*512];   // [0..8) = Ud1, [8..16) = Us1
DEVBUF float g_rec1[8ull*2048*512];
DEVBUF float g_rec0[8ull*4096*512];
DEVBUF float g_zf_part[8ull*32*512*64];
DEVBUF float g_zf     [32ull*512*64];
DEVBUF float g_mixp[4ull*32*512*64];   // modemix partials (i-split 4), [slot][o][m]
DEVBUF float g_mix [32ull*512*64];     // [slot][o(512)][m(64)]
DEVBUF float g_bF2048[2048*64];
DEVBUF float g_bI2048[2048*64];        // tf32-prerounded
DEVBUF float g_bF1024[1024*64];
DEVBUF float g_bI1024[1024*64];        // tf32-prerounded
DEVBUF float g_bt32[512ull*512];

// ===========================================================================
// Helpers (sm_80-baseline PTX: mma.sync tf32 / ldmatrix / cp.async)
// ===========================================================================
__device__ __forceinline__ uint32_t smem_u32(const void* p) {
    uint32_t a;
    asm("{ .reg .u64 t; cvta.to.shared.u64 t, %1; cvt.u32.u64 %0, t; }" : "=r"(a) : "l"(p));
    return a;
}
__device__ __forceinline__ void cp16(uint32_t smaddr, const void* g) {
    asm volatile("cp.async.cg.shared.global [%0], [%1], 16;" :: "r"(smaddr), "l"(g));
}
#define CP_COMMIT() asm volatile("cp.async.commit_group;" ::: "memory")
#define CP_WAIT2()  asm volatile("cp.async.wait_group 2;" ::: "memory")

__device__ __forceinline__ void ldsm4(uint32_t* r, uint32_t a) {
    asm volatile("ldmatrix.sync.aligned.m8n8.x4.shared.b16 {%0,%1,%2,%3}, [%4];"
        : "=r"(r[0]), "=r"(r[1]), "=r"(r[2]), "=r"(r[3]) : "r"(a));
}
__device__ __forceinline__ void ldsm2(uint32_t* r, uint32_t a) {
    asm volatile("ldmatrix.sync.aligned.m8n8.x2.shared.b16 {%0,%1}, [%2];"
        : "=r"(r[0]), "=r"(r[1]) : "r"(a));
}
__device__ __forceinline__ void mma_tf32(float* c, const uint32_t* a, const uint32_t* b) {
    asm volatile("mma.sync.aligned.m16n8k8.row.col.f32.tf32.tf32.f32 "
        "{%0,%1,%2,%3}, {%4,%5,%6,%7}, {%8,%9}, {%0,%1,%2,%3};"
        : "+f"(c[0]), "+f"(c[1]), "+f"(c[2]), "+f"(c[3])
        : "r"(a[0]), "r"(a[1]), "r"(a[2]), "r"(a[3]), "r"(b[0]), "r"(b[1]));
}
__device__ __forceinline__ uint32_t cvt_tf32(uint32_t u) {
    uint32_t o;
    float f = __uint_as_float(u);
    asm("cvt.rna.tf32.f32 %0, %1;" : "=r"(o) : "f"(f));
    return o;
}

// ===========================================================================
// tf32 mma GEMM (R6/R8-proven): C[32768,512] = A[32768,512] @ W[512,512]+bias
// BM=128, BN=128, BK=16, 3-stage cp.async, 8 warps (4m x 2n), 2 CTAs/SM.
// ===========================================================================
__global__ __launch_bounds__(256, 2) void gemm_tf32(
    const float* __restrict__ A, const float* __restrict__ Bt,
    const float* __restrict__ bias, float* __restrict__ C)
{
    __shared__ __align__(1024) float sA[3][128 * 16];
    __shared__ __align__(1024) float sB[3][128 * 16];

    const int tid  = threadIdx.x;
    const int wid  = tid >> 5;
    const int lane = tid & 31;
    const int m0 = blockIdx.y * 128;
    const int n0 = blockIdx.x * 128;
    const int wm = (wid >> 1) * 32;
    const int wn = (wid & 1) * 64;

    const uint32_t sA0 = smem_u32(sA);
    const uint32_t sB0 = smem_u32(sB);

    const int r0 = (tid + 0)   >> 2, c0 = (tid + 0)   & 3;
    const int r1 = (tid + 256) >> 2, c1 = (tid + 256) & 3;
    const uint32_t so0 = (uint32_t)(r0 * 64 + ((c0 ^ ((r0 >> 1) & 3)) * 16));
    const uint32_t so1 = (uint32_t)(r1 * 64 + ((c1 ^ ((r1 >> 1) & 3)) * 16));

    auto load_chunk = [&](int it, int s) {
        const int kb = it * 16;
        cp16(sA0 + s * 8192 + so0, A + (size_t)(m0 + r0) * 512 + kb + c0 * 4);
        cp16(sA0 + s * 8192 + so1, A + (size_t)(m0 + r1) * 512 + kb + c1 * 4);
        cp16(sB0 + s * 8192 + so0, Bt + (size_t)(n0 + r0) * 512 + kb + c0 * 4);
        cp16(sB0 + s * 8192 + so1, Bt + (size_t)(n0 + r1) * 512 + kb + c1 * 4);
        CP_COMMIT();
    };

    float acc[2][8][4];
#pragma unroll
    for (int i = 0; i < 2; i++)
#pragma unroll
        for (int j = 0; j < 8; j++)
#pragma unroll
            for (int k = 0; k < 4; k++) acc[i][j][k] = 0.f;

    const int la = lane & 15;
    const int ka = lane >> 4;
    const int lb = lane & 7;
    const int kb8 = (lane >> 3) & 1;

    load_chunk(0, 0);
    load_chunk(1, 1);

    const int NC = 32;
    for (int it = 0; it < NC; it++) {
        const int s = it % 3;
        if (it + 2 < NC) load_chunk(it + 2, (it + 2) % 3);
        else CP_COMMIT();
        CP_WAIT2();
        __syncthreads();

#pragma unroll
        for (int k8 = 0; k8 < 2; k8++) {
            uint32_t afr[2][4];
#pragma unroll
            for (int tm = 0; tm < 2; tm++) {
                int row = wm + tm * 16 + la;
                int k4 = k8 * 2 + ka;
                uint32_t addr = sA0 + s * 8192 + (uint32_t)(row * 64 + ((k4 ^ ((row >> 1) & 3)) * 16));
                ldsm4(afr[tm], addr);
#pragma unroll
                for (int q = 0; q < 4; q++) afr[tm][q] = cvt_tf32(afr[tm][q]);
            }
            uint32_t bfr[8][2];
#pragma unroll
            for (int n8 = 0; n8 < 8; n8++) {
                int row = wn + n8 * 8 + lb;
                int k4 = k8 * 2 + kb8;
                uint32_t addr = sB0 + s * 8192 + (uint32_t)(row * 64 + ((k4 ^ ((row >> 1) & 3)) * 16));
                ldsm2(bfr[n8], addr);
            }
#pragma unroll
            for (int tm = 0; tm < 2; tm++)
#pragma unroll
                for (int n8 = 0; n8 < 8; n8++)
                    mma_tf32(acc[tm][n8], afr[tm], bfr[n8]);
        }
        __syncthreads();
    }

    const int er = lane >> 2;
    const int ec = (lane & 3) * 2;
#pragma unroll
    for (int tm = 0; tm < 2; tm++) {
        const int m = m0 + wm + tm * 16 + er;
#pragma unroll
        for (int n8 = 0; n8 < 8; n8++) {
            const int n = n0 + wn + n8 * 8 + ec;
            const float b0 = bias[n], b1 = bias[n + 1];
            float2 v0 = make_float2(acc[tm][n8][0] + b0, acc[tm][n8][1] + b1);
            float2 v1 = make_float2(acc[tm][n8][2] + b0, acc[tm][n8][3] + b1);
            *(float2*)&C[(size_t)m * 512 + n]       = v0;
            *(float2*)&C[(size_t)(m + 8) * 512 + n] = v1;
        }
    }
}

__global__ void wgt_tf32(const float* __restrict__ W, float* __restrict__ Bt) {
    __shared__ float t[32][33];
    const int n0 = blockIdx.x * 32, k0 = blockIdx.y * 32;
    for (int i = threadIdx.y; i < 32; i += 8)
        t[i][threadIdx.x] = W[(size_t)(k0 + i) * 512 + n0 + threadIdx.x];
    __syncthreads();
    for (int i = threadIdx.y; i < 32; i += 8) {
        uint32_t v = cvt_tf32(__float_as_uint(t[threadIdx.x][i]));
        Bt[(size_t)(n0 + i) * 512 + k0 + threadIdx.x] = __uint_as_float(v);
    }
}

// ===========================================================================
// Inverse-DFT via tf32 mma: C[z][t][i] = bI[t][m] @ mixT[z][i][m]
// ===========================================================================
__global__ __launch_bounds__(256, 2) void invdft_tf32(
    const float* __restrict__ Abi, const float* __restrict__ Bm,
    float* __restrict__ C, int n2)
{
    __shared__ __align__(1024) float sA[3][128 * 16];
    __shared__ __align__(1024) float sB[3][128 * 16];

    const int tid  = threadIdx.x;
    const int wid  = tid >> 5;
    const int lane = tid & 31;
    const int m0 = blockIdx.y * 128;
    const int n0 = blockIdx.x * 128;
    const int z  = blockIdx.z;
    Bm += (size_t)z * 512 * 64;
    C  += (size_t)z * n2 * 512;
    const int wm = (wid >> 1) * 32;
    const int wn = (wid & 1) * 64;

    const uint32_t sA0 = smem_u32(sA);
    const uint32_t sB0 = smem_u32(sB);

    const int r0 = tid >> 2, c0 = tid & 3;
    const int r1 = r0 + 64;
    const uint32_t so0 = (uint32_t)(r0 * 64 + ((c0 ^ ((r0 >> 1) & 3)) * 16));
    const uint32_t so1 = (uint32_t)(r1 * 64 + ((c0 ^ ((r1 >> 1) & 3)) * 16));

    auto load_chunk = [&](int it, int s) {
        const int kb = it * 16;
        cp16(sA0 + s * 8192 + so0, Abi + (size_t)(m0 + r0) * 64 + kb + c0 * 4);
        cp16(sA0 + s * 8192 + so1, Abi + (size_t)(m0 + r1) * 64 + kb + c0 * 4);
        cp16(sB0 + s * 8192 + so0, Bm + (size_t)(n0 + r0) * 64 + kb + c0 * 4);
        cp16(sB0 + s * 8192 + so1, Bm + (size_t)(n0 + r1) * 64 + kb + c0 * 4);
        CP_COMMIT();
    };

    float acc[2][8][4];
#pragma unroll
    for (int i = 0; i < 2; i++)
#pragma unroll
        for (int j = 0; j < 8; j++)
#pragma unroll
            for (int k = 0; k < 4; k++) acc[i][j][k] = 0.f;

    const int la = lane & 15;
    const int ka = lane >> 4;
    const int b_r = wn + (lane & 7) + ((lane & 16) ? 8 : 0);
    const int b_u = (lane >> 3) & 1;

    load_chunk(0, 0);
    load_chunk(1, 1);

    const int NC = 4;
    for (int it = 0; it < NC; it++) {
        const int s = it % 3;
        if (it + 2 < NC) load_chunk(it + 2, (it + 2) % 3);
        else CP_COMMIT();
        CP_WAIT2();
        __syncthreads();

#pragma unroll
        for (int k8 = 0; k8 < 2; k8++) {
            uint32_t afr[2][4];
#pragma unroll
            for (int tm = 0; tm < 2; tm++) {
                int row = wm + tm * 16 + la;
                int k4 = k8 * 2 + ka;
                uint32_t addr = sA0 + s * 8192 + (uint32_t)(row * 64 + ((k4 ^ ((row >> 1) & 3)) * 16));
                ldsm4(afr[tm], addr);
            }
            uint32_t bfr[4][4];
#pragma unroll
            for (int p = 0; p < 4; p++) {
                int row = b_r + p * 16;
                int k4 = k8 * 2 + b_u;
                uint32_t addr = sB0 + s * 8192 + (uint32_t)(row * 64 + ((k4 ^ ((row >> 1) & 3)) * 16));
                ldsm4(bfr[p], addr);
#pragma unroll
                for (int q = 0; q < 4; q++) bfr[p][q] = cvt_tf32(bfr[p][q]);
            }
#pragma unroll
            for (int tm = 0; tm < 2; tm++)
#pragma unroll
                for (int p = 0; p < 4; p++) {
                    mma_tf32(acc[tm][p * 2 + 0], afr[tm], &bfr[p][0]);
                    mma_tf32(acc[tm][p * 2 + 1], afr[tm], &bfr[p][2]);
                }
        }
        __syncthreads();
    }

    const int er = lane >> 2;
    const int ec = (lane & 3) * 2;
#pragma unroll
    for (int tm = 0; tm < 2; tm++) {
        const int m = m0 + wm + tm * 16 + er;
#pragma unroll
        for (int n8 = 0; n8 < 8; n8++) {
            const int n = n0 + wn + n8 * 8 + ec;
            *(float2*)&C[(size_t)m * 512 + n]       = make_float2(acc[tm][n8][0], acc[tm][n8][1]);
            *(float2*)&C[(size_t)(m + 8) * 512 + n] = make_float2(acc[tm][n8][2], acc[tm][n8][3]);
        }
    }
}

// ===========================================================================
// Basis tables (bI pre-rounded to tf32)
// ===========================================================================
__device__ __forceinline__ void fill_tables(float* bF, float* bI, int t, int m, int n) {
    int x = (m < 32) ? m : (m - 32);
    long r = ((long)t * (long)x) % (long)n;
    double ang = 6.283185307179586476925286766559 * (double)r / (double)n;
    double c = cos(ang), s = sin(ang);
    bF[t*64 + m] = (m < 32) ? (float)c : (float)s;
    float vi;
    if (m == 0)          vi = 1.0f / (float)n;
    else if (m < 32)     vi = (float)(2.0 * c / (double)n);
    else if (m == 32)    vi = 0.0f;
    else                 vi = (float)(-2.0 * s / (double)n);
    bI[t*64 + m] = __uint_as_float(cvt_tf32(__float_as_uint(vi)));
}

__global__ __launch_bounds__(256) void basis_kernel() {
    int idx = blockIdx.x * 256 + threadIdx.x;
    if (idx < 2048*64) {
        int t = idx >> 6, m = idx & 63;
        fill_tables(g_bF2048, g_bI2048, t, m, 2048);
    }
    if (idx < 1024*64) {
        int t = idx >> 6, m = idx & 63;
        fill_tables(g_bF1024, g_bI1024, t, m, 1024);
    }
}

// ===========================================================================
// Encode: 2 channels per thread, float4 loads/stores (high MLP)
// ===========================================================================
__global__ __launch_bounds__(256) void encode_kernel(
    const float* __restrict__ cur, const float* __restrict__ ec_d,
    const float* __restrict__ ec_s, float* __restrict__ dco,
    float* __restrict__ sco, int n2)
{
    __shared__ float ed[128], es[128];
    if (threadIdx.x < 128) { ed[threadIdx.x] = ec_d[threadIdx.x]; es[threadIdx.x] = ec_s[threadIdx.x]; }
    __syncthreads();
    int idx = blockIdx.x * 256 + threadIdx.x;
    int total = 8 * n2 * 32;
    if (idx >= total) return;
    int cp = idx & 31;
    int bt = idx >> 5;
    const float* pe = cur + ((size_t)(128 * bt) + cp * 2) * 8;

    float4 ve[2][4];
#pragma unroll
    for (int cc = 0; cc < 2; cc++) {
        const float* p = pe + cc * 8;
        ve[cc][0] = *(const float4*)(p + 0);
        ve[cc][1] = *(const float4*)(p + 4);
        ve[cc][2] = *(const float4*)(p + 512);
        ve[cc][3] = *(const float4*)(p + 516);
    }
#pragma unroll
    for (int cc = 0; cc < 2; cc++) {
        float xa[16];
        xa[0]=ve[cc][0].x; xa[1]=ve[cc][0].y; xa[2]=ve[cc][0].z; xa[3]=ve[cc][0].w;
        xa[4]=ve[cc][1].x; xa[5]=ve[cc][1].y; xa[6]=ve[cc][1].z; xa[7]=ve[cc][1].w;
        xa[8]=ve[cc][2].x; xa[9]=ve[cc][2].y; xa[10]=ve[cc][2].z; xa[11]=ve[cc][2].w;
        xa[12]=ve[cc][3].x; xa[13]=ve[cc][3].y; xa[14]=ve[cc][3].z; xa[15]=ve[cc][3].w;
        float d[8] = {0,0,0,0,0,0,0,0}, s[8] = {0,0,0,0,0,0,0,0};
#pragma unroll
        for (int j = 0; j < 16; j++)
#pragma unroll
            for (int k = 0; k < 8; k++) {
                d[k] = fmaf(xa[j], ed[j * 8 + k], d[k]);
                s[k] = fmaf(xa[j], es[j * 8 + k], s[k]);
            }
        size_t ob = ((size_t)bt * 64 + cp * 2 + cc) * 8;
        *(float4*)&dco[ob]     = make_float4(d[0], d[1], d[2], d[3]);
        *(float4*)&dco[ob + 4] = make_float4(d[4], d[5], d[6], d[7]);
        *(float4*)&sco[ob]     = make_float4(s[0], s[1], s[2], s[3]);
        *(float4*)&sco[ob + 4] = make_float4(s[4], s[5], s[6], s[7]);
    }
}

// ===========================================================================
// Forward truncated DFT, BOTH levels in one launch (grid.z = 32)
// g<16: lev0 (n=2048,kc=256), else lev1 (n=1024,kc=128). slot = g.
// ===========================================================================
__global__ __launch_bounds__(256) void dftfwd_kernel(
    const float* __restrict__ zd0, const float* __restrict__ zs0,
    const float* __restrict__ zd1, const float* __restrict__ zs1,
    const float* __restrict__ bF0, const float* __restrict__ bF1,
    float* __restrict__ out_part)
{
    __shared__ float As[16][128];
    __shared__ float Bs[16][64];
    const int tid = threadIdx.x;
    const int g = blockIdx.z;
    const float* z;
    const float* bF;
    int n, kchunk;
    if (g < 16) { z = (g < 8) ? zd0 : zs0; bF = bF0; n = 2048; kchunk = 256; }
    else        { z = (g < 24) ? zd1 : zs1; bF = bF1; n = 1024; kchunk = 128; }
    z += (size_t)(g & 7) * n * 512;
    const int i0 = blockIdx.x * 128;
    const int tbase = blockIdx.y * kchunk;

    const int tx = tid & 15;
    const int ty = tid >> 4;

    float acc[8][4];
#pragma unroll
    for (int i = 0; i < 8; i++)
#pragma unroll
        for (int j = 0; j < 4; j++) acc[i][j] = 0.f;

    for (int tc = 0; tc < kchunk; tc += 16) {
#pragma unroll
        for (int p = 0; p < 2; p++) {
            int tr = (tid >> 5) + p * 8;
            int ic = (tid & 31) * 4;
            *(float4*)&As[tr][ic] = *(const float4*)&z[(size_t)(tbase + tc + tr) * 512 + i0 + ic];
        }
        {
            int tr = tid >> 4;
            int mc = (tid & 15) * 4;
            *(float4*)&Bs[tr][mc] = *(const float4*)&bF[(size_t)(tbase + tc + tr) * 64 + mc];
        }
        __syncthreads();
#pragma unroll
        for (int kk = 0; kk < 16; kk++) {
            float4 a0 = *(const float4*)&As[kk][ty * 8 + 0];
            float4 a1 = *(const float4*)&As[kk][ty * 8 + 4];
            float4 bv = *(const float4*)&Bs[kk][tx * 4];
            float av[8] = {a0.x,a0.y,a0.z,a0.w,a1.x,a1.y,a1.z,a1.w};
            float bb[4] = {bv.x,bv.y,bv.z,bv.w};
#pragma unroll
            for (int i = 0; i < 8; i++)
#pragma unroll
                for (int j = 0; j < 4; j++)
                    acc[i][j] = fmaf(av[i], bb[j], acc[i][j]);
        }
        __syncthreads();
    }
#pragma unroll
    for (int i = 0; i < 8; i++) {
        size_t base = (((size_t)blockIdx.y * 32 + g) * 512 + (i0 + ty * 8 + i)) * 64 + tx * 4;
        float4 o = make_float4(acc[i][0], acc[i][1], acc[i][2], acc[i][3]);
        *(float4*)&out_part[base] = o;
    }
}

__global__ __launch_bounds__(256) void reduce_parts(
    const float* __restrict__ part, float* __restrict__ out, int count, int nparts)
{
    int e = blockIdx.x * 256 + threadIdx.x;
    if (e >= count) return;
    float s = 0.f;
    for (int p = 0; p < nparts; p++) s += part[(size_t)p * count + e];
    out[e] = s;
}

// ===========================================================================
// Mode mixing, both levels, i-split 4. Output layout [slot][o][m] (m contig).
// ===========================================================================
__global__ __launch_bounds__(256) void modemix_kernel(
    const float* __restrict__ zf,
    const float* __restrict__ waR, const float* __restrict__ waI,
    const float* __restrict__ wbR, const float* __restrict__ wbI,
    const float* __restrict__ wcR, const float* __restrict__ wcI,
    float* __restrict__ out_part)
{
    __shared__ float zdS[2][8][8][64];
    __shared__ float zsS[2][8][8][64];
    const int x = threadIdx.x & 31;
    const int q = threadIdx.x >> 5;
    const int o = blockIdx.x * 8 + q;
    const int i0 = blockIdx.y * 128;

    float uR[16], uI[16], sR[16], sI[16];
#pragma unroll
    for (int b = 0; b < 16; b++) { uR[b]=0.f; uI[b]=0.f; sR[b]=0.f; sI[b]=0.f; }

    for (int ic = 0; ic < 128; ic += 8) {
        __syncthreads();
        for (int e = threadIdx.x; e < 8192; e += 256) {
            int lev = e >> 12, r = e & 4095;
            int b = r >> 9, rr = r & 511, ii = rr >> 6, xx = rr & 63;
            size_t gidx = ((size_t)b * 512 + (i0 + ic + ii)) * 64 + xx;
            size_t lbase = (size_t)lev * 16 * 512 * 64;
            zdS[lev][b][ii][xx] = zf[lbase + gidx];
            zsS[lev][b][ii][xx] = zf[lbase + 8ull * 512 * 64 + gidx];
        }
        __syncthreads();
#pragma unroll 2
        for (int ii = 0; ii < 8; ii++) {
            int i = i0 + ic + ii;
            size_t wbase = ((size_t)i * 512 + o) * 32 + x;
            float war = waR[wbase], wai = waI[wbase];
            float wbr = wbR[wbase], wbi = wbI[wbase];
            float wcr = wcR[wbase], wci = wcI[wbase];
#pragma unroll
            for (int lev = 0; lev < 2; lev++)
#pragma unroll
            for (int b = 0; b < 8; b++) {
                int bb = lev * 8 + b;
                float zr = zdS[lev][b][ii][x];
                float zi = -zdS[lev][b][ii][32 + x];
                float sr = zsS[lev][b][ii][x];
                float si = -zsS[lev][b][ii][32 + x];
                uR[bb] = fmaf(zr, war, uR[bb]); uR[bb] = fmaf(-zi, wai, uR[bb]);
                uR[bb] = fmaf(sr, wbr, uR[bb]); uR[bb] = fmaf(-si, wbi, uR[bb]);
                uI[bb] = fmaf(zr, wai, uI[bb]); uI[bb] = fmaf(zi, war, uI[bb]);
                uI[bb] = fmaf(sr, wbi, uI[bb]); uI[bb] = fmaf(si, wbr, uI[bb]);
                sR[bb] = fmaf(zr, wcr, sR[bb]); sR[bb] = fmaf(-zi, wci, sR[bb]);
                sI[bb] = fmaf(zr, wci, sI[bb]); sI[bb] = fmaf(zi, wcr, sI[bb]);
            }
        }
    }
#pragma unroll
    for (int bb = 0; bb < 16; bb++) {
        int lev = bb >> 3, b = bb & 7;
        size_t slotU = (size_t)blockIdx.y * 32 + lev * 16 + b;
        size_t slotS = slotU + 8;
        out_part[(slotU * 512 + o) * 64 + x]      = uR[bb];
        out_part[(slotU * 512 + o) * 64 + 32 + x] = uI[bb];
        out_part[(slotS * 512 + o) * 64 + x]      = sR[bb];
        out_part[(slotS * 512 + o) * 64 + 32 + x] = sI[bb];
    }
}

// ===========================================================================
// Recon with fused t0 (level 1), 2 channels/thread
// ===========================================================================
__global__ __launch_bounds__(256) void recon_t0_kernel(
    const float* __restrict__ cur, const float* __restrict__ us,
    const float* __restrict__ ud, const float* __restrict__ rc_e,
    const float* __restrict__ rc_o, const float* __restrict__ t0w,
    const float* __restrict__ t0b, float* __restrict__ out, int n2)
{
    __shared__ float re[128], ro[128], w[64], bb[8];
    if (threadIdx.x < 128) { re[threadIdx.x] = rc_e[threadIdx.x]; ro[threadIdx.x] = rc_o[threadIdx.x]; }
    if (threadIdx.x < 64)  w[threadIdx.x] = t0w[threadIdx.x];
    if (threadIdx.x >= 64 && threadIdx.x < 72) bb[threadIdx.x - 64] = t0b[threadIdx.x - 64];
    __syncthreads();
    int idx = blockIdx.x * 256 + threadIdx.x;
    int total = 8 * n2 * 32;
    if (idx >= total) return;
    int cp = idx & 31;
    int bt = idx >> 5;

    float4 vc[2][2], vu[2][2], vd[2][2];
#pragma unroll
    for (int cc = 0; cc < 2; cc++) {
        size_t base = ((size_t)bt * 64 + cp * 2 + cc) * 8;
        vc[cc][0] = *(const float4*)(cur + base); vc[cc][1] = *(const float4*)(cur + base + 4);
        vu[cc][0] = *(const float4*)(us + base);  vu[cc][1] = *(const float4*)(us + base + 4);
        vd[cc][0] = *(const float4*)(ud + base);  vd[cc][1] = *(const float4*)(ud + base + 4);
    }
#pragma unroll
    for (int cc = 0; cc < 2; cc++) {
        int c = cp * 2 + cc;
        float sv[8] = {vc[cc][0].x,vc[cc][0].y,vc[cc][0].z,vc[cc][0].w,
                       vc[cc][1].x,vc[cc][1].y,vc[cc][1].z,vc[cc][1].w};
        float uu[8] = {vu[cc][0].x,vu[cc][0].y,vu[cc][0].z,vu[cc][0].w,
                       vu[cc][1].x,vu[cc][1].y,vu[cc][1].z,vu[cc][1].w};
        float v[16];
        v[8]=vd[cc][0].x; v[9]=vd[cc][0].y; v[10]=vd[cc][0].z; v[11]=vd[cc][0].w;
        v[12]=vd[cc][1].x; v[13]=vd[cc][1].y; v[14]=vd[cc][1].z; v[15]=vd[cc][1].w;
#pragma unroll
        for (int k = 0; k < 8; k++) {
            float t = bb[k];
#pragma unroll
            for (int j = 0; j < 8; j++) t = fmaf(sv[j], w[j * 8 + k], t);
            v[k] = t + uu[k];
        }
        float xe[8] = {0,0,0,0,0,0,0,0}, xo[8] = {0,0,0,0,0,0,0,0};
#pragma unroll
        for (int j = 0; j < 16; j++)
#pragma unroll
            for (int k = 0; k < 8; k++) {
                xe[k] = fmaf(v[j], re[j * 8 + k], xe[k]);
                xo[k] = fmaf(v[j], ro[j * 8 + k], xo[k]);
            }
        float* pe = out + ((size_t)(128 * bt + c)) * 8;
        *(float4*)(pe + 0)   = make_float4(xe[0], xe[1], xe[2], xe[3]);
        *(float4*)(pe + 4)   = make_float4(xe[4], xe[5], xe[6], xe[7]);
        *(float4*)(pe + 512) = make_float4(xo[0], xo[1], xo[2], xo[3]);
        *(float4*)(pe + 516) = make_float4(xo[4], xo[5], xo[6], xo[7]);
    }
}

// Recon (level 0), 2 channels/thread
__global__ __launch_bounds__(256) void recon_kernel(
    const float* __restrict__ cur, const float* __restrict__ us,
    const float* __restrict__ ud, const float* __restrict__ rc_e,
    const float* __restrict__ rc_o, float* __restrict__ out, int n2)
{
    __shared__ float re[128], ro[128];
    if (threadIdx.x < 128) { re[threadIdx.x] = rc_e[threadIdx.x]; ro[threadIdx.x] = rc_o[threadIdx.x]; }
    __syncthreads();
    int idx = blockIdx.x * 256 + threadIdx.x;
    int total = 8 * n2 * 32;
    if (idx >= total) return;
    int cp = idx & 31;
    int bt = idx >> 5;

    float4 vc[2][2], vu[2][2], vd[2][2];
#pragma unroll
    for (int cc = 0; cc < 2; cc++) {
        size_t base = ((size_t)bt * 64 + cp * 2 + cc) * 8;
        vc[cc][0] = *(const float4*)(cur + base); vc[cc][1] = *(const float4*)(cur + base + 4);
        vu[cc][0] = *(const float4*)(us + base);  vu[cc][1] = *(const float4*)(us + base + 4);
        vd[cc][0] = *(const float4*)(ud + base);  vd[cc][1] = *(const float4*)(ud + base + 4);
    }
#pragma unroll
    for (int cc = 0; cc < 2; cc++) {
        int c = cp * 2 + cc;
        float v[16];
        v[0]=vc[cc][0].x+vu[cc][0].x; v[1]=vc[cc][0].y+vu[cc][0].y;
        v[2]=vc[cc][0].z+vu[cc][0].z; v[3]=vc[cc][0].w+vu[cc][0].w;
        v[4]=vc[cc][1].x+vu[cc][1].x; v[5]=vc[cc][1].y+vu[cc][1].y;
        v[6]=vc[cc][1].z+vu[cc][1].z; v[7]=vc[cc][1].w+vu[cc][1].w;
        v[8]=vd[cc][0].x; v[9]=vd[cc][0].y; v[10]=vd[cc][0].z; v[11]=vd[cc][0].w;
        v[12]=vd[cc][1].x; v[13]=vd[cc][1].y; v[14]=vd[cc][1].z; v[15]=vd[cc][1].w;
        float xe[8] = {0,0,0,0,0,0,0,0}, xo[8] = {0,0,0,0,0,0,0,0};
#pragma unroll
        for (int j = 0; j < 16; j++)
#pragma unroll
            for (int k = 0; k < 8; k++) {
                xe[k] = fmaf(v[j], re[j * 8 + k], xe[k]);
                xo[k] = fmaf(v[j], ro[j * 8 + k], xo[k]);
            }
        float* pe = out + ((size_t)(128 * bt + c)) * 8;
        *(float4*)(pe + 0)   = make_float4(xe[0], xe[1], xe[2], xe[3]);
        *(float4*)(pe + 4)   = make_float4(xe[4], xe[5], xe[6], xe[7]);
        *(float4*)(pe + 512) = make_float4(xo[0], xo[1], xo[2], xo[3]);
        *(float4*)(pe + 516) = make_float4(xo[4], xo[5], xo[6], xo[7]);
    }
}

// ===========================================================================
// Host orchestration
// ===========================================================================
#define SYM(p, s) do { void* _t; cudaGetSymbolAddress(&_t, s); p = (decltype(p))_t; } while (0)

extern "C" void kernel_launch(void* const* d_in, const int* in_sizes, int n_in,
                              void* d_out, int out_size)
{
    const float* x        = (const float*)d_in[0];
    const float* lin_in_w = (const float*)d_in[1];
    const float* lin_in_b = (const float*)d_in[2];
    const float* lin_out_w= (const float*)d_in[3];
    const float* lin_out_b= (const float*)d_in[4];
    const float* t0_w     = (const float*)d_in[5];
    const float* t0_b     = (const float*)d_in[6];
    const float* wA_re    = (const float*)d_in[7];
    const float* wA_im    = (const float*)d_in[8];
    const float* wB_re    = (const float*)d_in[9];
    const float* wB_im    = (const float*)d_in[10];
    const float* wC_re    = (const float*)d_in[11];
    const float* wC_im    = (const float*)d_in[12];
    const float* ec_s     = (const float*)d_in[13];
    const float* ec_d     = (const float*)d_in[14];
    const float* rc_e     = (const float*)d_in[15];
    const float* rc_o     = (const float*)d_in[16];

    float *pz, *pd0, *ps0, *pd1, *ps1, *pUS0, *pUS1;
    float *prec1, *prec0, *pzfp, *pzf, *pmixp, *pmix;
    float *pbF2, *pbI2, *pbF1, *pbI1, *pbt32;
    SYM(pz, g_z); SYM(pd0, g_d0); SYM(ps0, g_s0);
    SYM(pd1, g_d1); SYM(ps1, g_s1);
    SYM(pUS0, g_US0); SYM(pUS1, g_US1);
    SYM(prec1, g_rec1); SYM(prec0, g_rec0);
    SYM(pzfp, g_zf_part); SYM(pzf, g_zf);
    SYM(pmixp, g_mixp); SYM(pmix, g_mix);
    SYM(pbF2, g_bF2048); SYM(pbI2, g_bI2048); SYM(pbF1, g_bF1024); SYM(pbI1, g_bI1024);
    SYM(pbt32, g_bt32);

    const int ZFCOUNT  = 32 * 512 * 64;
    const int MIXCOUNT = 32 * 512 * 64;

    // 0) basis tables
    basis_kernel<<<512, 256>>>();

    // 1) lin_in via tf32 mma
    wgt_tf32<<<dim3(16, 16), dim3(32, 8)>>>(lin_in_w, pbt32);
    gemm_tf32<<<dim3(4, 256), 256>>>(x, pbt32, lin_in_b, pz);

    // 2) both encodes
    encode_kernel<<<(8 * 2048 * 32) / 256, 256>>>(pz, ec_d, ec_s, pd0, ps0, 2048);
    encode_kernel<<<(8 * 1024 * 32) / 256, 256>>>(ps0, ec_d, ec_s, pd1, ps1, 1024);

    // 3) forward DFTs, both levels, one launch
    dftfwd_kernel<<<dim3(4, 8, 32), 256>>>(pd0, ps0, pd1, ps1, pbF2, pbF1, pzfp);
    reduce_parts<<<(ZFCOUNT + 255) / 256, 256>>>(pzfp, pzf, ZFCOUNT, 8);

    // 4) single modemix over both levels, i-split 4, [slot][o][m] output
    modemix_kernel<<<dim3(64, 4), 256>>>(pzf, wA_re, wA_im, wB_re, wB_im,
                                         wC_re, wC_im, pmixp);
    reduce_parts<<<(MIXCOUNT + 255) / 256, 256>>>(pmixp, pmix, MIXCOUNT, 4);

    // 5) inverse DFTs via tf32 mma (z-batched)
    invdft_tf32<<<dim3(4, 16, 16), 256>>>(pbI2, pmix, pUS0, 2048);
    invdft_tf32<<<dim3(4, 8, 16), 256>>>(pbI1, pmix + 16ull * 512 * 64, pUS1, 1024);

    // 6) reconstruction (t0 fused into level-1 recon)
    recon_t0_kernel<<<(8 * 1024 * 32) / 256, 256>>>(
        ps1, pUS1 + 8ull * 1024 * 512, pUS1, rc_e, rc_o, t0_w, t0_b, prec1, 1024);
    recon_kernel<<<(8 * 2048 * 32) / 256, 256>>>(
        prec1, pUS0 + 8ull * 2048 * 512, pUS0, rc_e, rc_o, prec0, 2048);

    // 7) lin_out via tf32 mma -> d_out
    wgt_tf32<<<dim3(16, 16), dim3(32, 8)>>>(lin_out_w, pbt32);
    gemm_tf32<<<dim3(4, 256), 256>>>(prec0, pbt32, lin_out_b, (float*)d_out);

    (void)in_sizes; (void)n_in; (void)out_size;
}

// round 12
// speedup vs baseline: 1.0584x; 1.0134x over previous
#include <cuda_runtime.h>
#include <cuda_bf16.h>
#include <math.h>
#include <stdint.h>

// Problem constants: B=8, T=4096, H=8, D=64, CK=512, K=8, C=64, MODES=32, L=2

#define DEVBUF __device__ __align__(256)
DEVBUF float g_z   [8ull*4096*512];
DEVBUF float g_d0  [8ull*2048*512];
DEVBUF float g_s0  [8ull*2048*512];
DEVBUF float g_d1  [8ull*1024*512];
DEVBUF float g_s1  [8ull*1024*512];
DEVBUF float g_US0 [16ull*2048*512];   // [0..8) = Ud0 batches, [8..16) = Us0
DEVBUF float g_US1 [16ull*1024*512];   // [0..8) = Ud1, [8..16) = Us1
DEVBUF float g_rec1[8ull*2048*512];
DEVBUF float g_rec0[8ull*4096*512];
DEVBUF float g_zf_part[8ull*32*512*64];
DEVBUF float g_zf     [32ull*512*64];
DEVBUF float g_mixp[8ull*32*512*64];   // modemix partials (i-split 8), [part][slot][o][m]
DEVBUF float g_mix [32ull*512*64];     // [slot][o(512)][m(64)]
DEVBUF float g_bF2048[2048*64];
DEVBUF float g_bI2048[2048*64];        // tf32-prerounded
DEVBUF float g_bF1024[1024*64];
DEVBUF float g_bI1024[1024*64];        // tf32-prerounded
DEVBUF float g_bt32[512ull*512];

// ===========================================================================
// Helpers (sm_80-baseline PTX: mma.sync tf32 / ldmatrix / cp.async)
// ===========================================================================
__device__ __forceinline__ uint32_t smem_u32(const void* p) {
    uint32_t a;
    asm("{ .reg .u64 t; cvta.to.shared.u64 t, %1; cvt.u32.u64 %0, t; }" : "=r"(a) : "l"(p));
    return a;
}
__device__ __forceinline__ void cp16(uint32_t smaddr, const void* g) {
    asm volatile("cp.async.cg.shared.global [%0], [%1], 16;" :: "r"(smaddr), "l"(g));
}
#define CP_COMMIT() asm volatile("cp.async.commit_group;" ::: "memory")
#define CP_WAIT2()  asm volatile("cp.async.wait_group 2;" ::: "memory")

__device__ __forceinline__ void ldsm4(uint32_t* r, uint32_t a) {
    asm volatile("ldmatrix.sync.aligned.m8n8.x4.shared.b16 {%0,%1,%2,%3}, [%4];"
        : "=r"(r[0]), "=r"(r[1]), "=r"(r[2]), "=r"(r[3]) : "r"(a));
}
__device__ __forceinline__ void ldsm2(uint32_t* r, uint32_t a) {
    asm volatile("ldmatrix.sync.aligned.m8n8.x2.shared.b16 {%0,%1}, [%2];"
        : "=r"(r[0]), "=r"(r[1]) : "r"(a));
}
__device__ __forceinline__ void mma_tf32(float* c, const uint32_t* a, const uint32_t* b) {
    asm volatile("mma.sync.aligned.m16n8k8.row.col.f32.tf32.tf32.f32 "
        "{%0,%1,%2,%3}, {%4,%5,%6,%7}, {%8,%9}, {%0,%1,%2,%3};"
        : "+f"(c[0]), "+f"(c[1]), "+f"(c[2]), "+f"(c[3])
        : "r"(a[0]), "r"(a[1]), "r"(a[2]), "r"(a[3]), "r"(b[0]), "r"(b[1]));
}
__device__ __forceinline__ uint32_t cvt_tf32(uint32_t u) {
    uint32_t o;
    float f = __uint_as_float(u);
    asm("cvt.rna.tf32.f32 %0, %1;" : "=r"(o) : "f"(f));
    return o;
}

// ===========================================================================
// tf32 mma GEMM (R6/R8-proven): C[32768,512] = A[32768,512] @ W[512,512]+bias
// ===========================================================================
__global__ __launch_bounds__(256, 2) void gemm_tf32(
    const float* __restrict__ A, const float* __restrict__ Bt,
    const float* __restrict__ bias, float* __restrict__ C)
{
    __shared__ __align__(1024) float sA[3][128 * 16];
    __shared__ __align__(1024) float sB[3][128 * 16];

    const int tid  = threadIdx.x;
    const int wid  = tid >> 5;
    const int lane = tid & 31;
    const int m0 = blockIdx.y * 128;
    const int n0 = blockIdx.x * 128;
    const int wm = (wid >> 1) * 32;
    const int wn = (wid & 1) * 64;

    const uint32_t sA0 = smem_u32(sA);
    const uint32_t sB0 = smem_u32(sB);

    const int r0 = (tid + 0)   >> 2, c0 = (tid + 0)   & 3;
    const int r1 = (tid + 256) >> 2, c1 = (tid + 256) & 3;
    const uint32_t so0 = (uint32_t)(r0 * 64 + ((c0 ^ ((r0 >> 1) & 3)) * 16));
    const uint32_t so1 = (uint32_t)(r1 * 64 + ((c1 ^ ((r1 >> 1) & 3)) * 16));

    auto load_chunk = [&](int it, int s) {
        const int kb = it * 16;
        cp16(sA0 + s * 8192 + so0, A + (size_t)(m0 + r0) * 512 + kb + c0 * 4);
        cp16(sA0 + s * 8192 + so1, A + (size_t)(m0 + r1) * 512 + kb + c1 * 4);
        cp16(sB0 + s * 8192 + so0, Bt + (size_t)(n0 + r0) * 512 + kb + c0 * 4);
        cp16(sB0 + s * 8192 + so1, Bt + (size_t)(n0 + r1) * 512 + kb + c1 * 4);
        CP_COMMIT();
    };

    float acc[2][8][4];
#pragma unroll
    for (int i = 0; i < 2; i++)
#pragma unroll
        for (int j = 0; j < 8; j++)
#pragma unroll
            for (int k = 0; k < 4; k++) acc[i][j][k] = 0.f;

    const int la = lane & 15;
    const int ka = lane >> 4;
    const int lb = lane & 7;
    const int kb8 = (lane >> 3) & 1;

    load_chunk(0, 0);
    load_chunk(1, 1);

    const int NC = 32;
    for (int it = 0; it < NC; it++) {
        const int s = it % 3;
        if (it + 2 < NC) load_chunk(it + 2, (it + 2) % 3);
        else CP_COMMIT();
        CP_WAIT2();
        __syncthreads();

#pragma unroll
        for (int k8 = 0; k8 < 2; k8++) {
            uint32_t afr[2][4];
#pragma unroll
            for (int tm = 0; tm < 2; tm++) {
                int row = wm + tm * 16 + la;
                int k4 = k8 * 2 + ka;
                uint32_t addr = sA0 + s * 8192 + (uint32_t)(row * 64 + ((k4 ^ ((row >> 1) & 3)) * 16));
                ldsm4(afr[tm], addr);
#pragma unroll
                for (int q = 0; q < 4; q++) afr[tm][q] = cvt_tf32(afr[tm][q]);
            }
            uint32_t bfr[8][2];
#pragma unroll
            for (int n8 = 0; n8 < 8; n8++) {
                int row = wn + n8 * 8 + lb;
                int k4 = k8 * 2 + kb8;
                uint32_t addr = sB0 + s * 8192 + (uint32_t)(row * 64 + ((k4 ^ ((row >> 1) & 3)) * 16));
                ldsm2(bfr[n8], addr);
            }
#pragma unroll
            for (int tm = 0; tm < 2; tm++)
#pragma unroll
                for (int n8 = 0; n8 < 8; n8++)
                    mma_tf32(acc[tm][n8], afr[tm], bfr[n8]);
        }
        __syncthreads();
    }

    const int er = lane >> 2;
    const int ec = (lane & 3) * 2;
#pragma unroll
    for (int tm = 0; tm < 2; tm++) {
        const int m = m0 + wm + tm * 16 + er;
#pragma unroll
        for (int n8 = 0; n8 < 8; n8++) {
            const int n = n0 + wn + n8 * 8 + ec;
            const float b0 = bias[n], b1 = bias[n + 1];
            float2 v0 = make_float2(acc[tm][n8][0] + b0, acc[tm][n8][1] + b1);
            float2 v1 = make_float2(acc[tm][n8][2] + b0, acc[tm][n8][3] + b1);
            *(float2*)&C[(size_t)m * 512 + n]       = v0;
            *(float2*)&C[(size_t)(m + 8) * 512 + n] = v1;
        }
    }
}

__global__ void wgt_tf32(const float* __restrict__ W, float* __restrict__ Bt) {
    __shared__ float t[32][33];
    const int n0 = blockIdx.x * 32, k0 = blockIdx.y * 32;
    for (int i = threadIdx.y; i < 32; i += 8)
        t[i][threadIdx.x] = W[(size_t)(k0 + i) * 512 + n0 + threadIdx.x];
    __syncthreads();
    for (int i = threadIdx.y; i < 32; i += 8) {
        uint32_t v = cvt_tf32(__float_as_uint(t[threadIdx.x][i]));
        Bt[(size_t)(n0 + i) * 512 + k0 + threadIdx.x] = __uint_as_float(v);
    }
}

// ===========================================================================
// Inverse-DFT via tf32 mma: C[z][t][i] = bI[t][m] @ mixT[z][i][m]
// ===========================================================================
__global__ __launch_bounds__(256, 2) void invdft_tf32(
    const float* __restrict__ Abi, const float* __restrict__ Bm,
    float* __restrict__ C, int n2)
{
    __shared__ __align__(1024) float sA[3][128 * 16];
    __shared__ __align__(1024) float sB[3][128 * 16];

    const int tid  = threadIdx.x;
    const int wid  = tid >> 5;
    const int lane = tid & 31;
    const int m0 = blockIdx.y * 128;
    const int n0 = blockIdx.x * 128;
    const int z  = blockIdx.z;
    Bm += (size_t)z * 512 * 64;
    C  += (size_t)z * n2 * 512;
    const int wm = (wid >> 1) * 32;
    const int wn = (wid & 1) * 64;

    const uint32_t sA0 = smem_u32(sA);
    const uint32_t sB0 = smem_u32(sB);

    const int r0 = tid >> 2, c0 = tid & 3;
    const int r1 = r0 + 64;
    const uint32_t so0 = (uint32_t)(r0 * 64 + ((c0 ^ ((r0 >> 1) & 3)) * 16));
    const uint32_t so1 = (uint32_t)(r1 * 64 + ((c0 ^ ((r1 >> 1) & 3)) * 16));

    auto load_chunk = [&](int it, int s) {
        const int kb = it * 16;
        cp16(sA0 + s * 8192 + so0, Abi + (size_t)(m0 + r0) * 64 + kb + c0 * 4);
        cp16(sA0 + s * 8192 + so1, Abi + (size_t)(m0 + r1) * 64 + kb + c0 * 4);
        cp16(sB0 + s * 8192 + so0, Bm + (size_t)(n0 + r0) * 64 + kb + c0 * 4);
        cp16(sB0 + s * 8192 + so1, Bm + (size_t)(n0 + r1) * 64 + kb + c0 * 4);
        CP_COMMIT();
    };

    float acc[2][8][4];
#pragma unroll
    for (int i = 0; i < 2; i++)
#pragma unroll
        for (int j = 0; j < 8; j++)
#pragma unroll
            for (int k = 0; k < 4; k++) acc[i][j][k] = 0.f;

    const int la = lane & 15;
    const int ka = lane >> 4;
    const int b_r = wn + (lane & 7) + ((lane & 16) ? 8 : 0);
    const int b_u = (lane >> 3) & 1;

    load_chunk(0, 0);
    load_chunk(1, 1);

    const int NC = 4;
    for (int it = 0; it < NC; it++) {
        const int s = it % 3;
        if (it + 2 < NC) load_chunk(it + 2, (it + 2) % 3);
        else CP_COMMIT();
        CP_WAIT2();
        __syncthreads();

#pragma unroll
        for (int k8 = 0; k8 < 2; k8++) {
            uint32_t afr[2][4];
#pragma unroll
            for (int tm = 0; tm < 2; tm++) {
                int row = wm + tm * 16 + la;
                int k4 = k8 * 2 + ka;
                uint32_t addr = sA0 + s * 8192 + (uint32_t)(row * 64 + ((k4 ^ ((row >> 1) & 3)) * 16));
                ldsm4(afr[tm], addr);
            }
            uint32_t bfr[4][4];
#pragma unroll
            for (int p = 0; p < 4; p++) {
                int row = b_r + p * 16;
                int k4 = k8 * 2 + b_u;
                uint32_t addr = sB0 + s * 8192 + (uint32_t)(row * 64 + ((k4 ^ ((row >> 1) & 3)) * 16));
                ldsm4(bfr[p], addr);
#pragma unroll
                for (int q = 0; q < 4; q++) bfr[p][q] = cvt_tf32(bfr[p][q]);
            }
#pragma unroll
            for (int tm = 0; tm < 2; tm++)
#pragma unroll
                for (int p = 0; p < 4; p++) {
                    mma_tf32(acc[tm][p * 2 + 0], afr[tm], &bfr[p][0]);
                    mma_tf32(acc[tm][p * 2 + 1], afr[tm], &bfr[p][2]);
                }
        }
        __syncthreads();
    }

    const int er = lane >> 2;
    const int ec = (lane & 3) * 2;
#pragma unroll
    for (int tm = 0; tm < 2; tm++) {
        const int m = m0 + wm + tm * 16 + er;
#pragma unroll
        for (int n8 = 0; n8 < 8; n8++) {
            const int n = n0 + wn + n8 * 8 + ec;
            *(float2*)&C[(size_t)m * 512 + n]       = make_float2(acc[tm][n8][0], acc[tm][n8][1]);
            *(float2*)&C[(size_t)(m + 8) * 512 + n] = make_float2(acc[tm][n8][2], acc[tm][n8][3]);
        }
    }
}

// ===========================================================================
// Basis tables (bI pre-rounded to tf32)
// ===========================================================================
__device__ __forceinline__ void fill_tables(float* bF, float* bI, int t, int m, int n) {
    int x = (m < 32) ? m : (m - 32);
    long r = ((long)t * (long)x) % (long)n;
    double ang = 6.283185307179586476925286766559 * (double)r / (double)n;
    double c = cos(ang), s = sin(ang);
    bF[t*64 + m] = (m < 32) ? (float)c : (float)s;
    float vi;
    if (m == 0)          vi = 1.0f / (float)n;
    else if (m < 32)     vi = (float)(2.0 * c / (double)n);
    else if (m == 32)    vi = 0.0f;
    else                 vi = (float)(-2.0 * s / (double)n);
    bI[t*64 + m] = __uint_as_float(cvt_tf32(__float_as_uint(vi)));
}

__global__ __launch_bounds__(256) void basis_kernel() {
    int idx = blockIdx.x * 256 + threadIdx.x;
    if (idx < 2048*64) {
        int t = idx >> 6, m = idx & 63;
        fill_tables(g_bF2048, g_bI2048, t, m, 2048);
    }
    if (idx < 1024*64) {
        int t = idx >> 6, m = idx & 63;
        fill_tables(g_bF1024, g_bI1024, t, m, 1024);
    }
}

// ===========================================================================
// Encode: 2 channels per thread, float4 loads/stores (high MLP)
// ===========================================================================
__global__ __launch_bounds__(256) void encode_kernel(
    const float* __restrict__ cur, const float* __restrict__ ec_d,
    const float* __restrict__ ec_s, float* __restrict__ dco,
    float* __restrict__ sco, int n2)
{
    __shared__ float ed[128], es[128];
    if (threadIdx.x < 128) { ed[threadIdx.x] = ec_d[threadIdx.x]; es[threadIdx.x] = ec_s[threadIdx.x]; }
    __syncthreads();
    int idx = blockIdx.x * 256 + threadIdx.x;
    int total = 8 * n2 * 32;
    if (idx >= total) return;
    int cp = idx & 31;
    int bt = idx >> 5;
    const float* pe = cur + ((size_t)(128 * bt) + cp * 2) * 8;

    float4 ve[2][4];
#pragma unroll
    for (int cc = 0; cc < 2; cc++) {
        const float* p = pe + cc * 8;
        ve[cc][0] = *(const float4*)(p + 0);
        ve[cc][1] = *(const float4*)(p + 4);
        ve[cc][2] = *(const float4*)(p + 512);
        ve[cc][3] = *(const float4*)(p + 516);
    }
#pragma unroll
    for (int cc = 0; cc < 2; cc++) {
        float xa[16];
        xa[0]=ve[cc][0].x; xa[1]=ve[cc][0].y; xa[2]=ve[cc][0].z; xa[3]=ve[cc][0].w;
        xa[4]=ve[cc][1].x; xa[5]=ve[cc][1].y; xa[6]=ve[cc][1].z; xa[7]=ve[cc][1].w;
        xa[8]=ve[cc][2].x; xa[9]=ve[cc][2].y; xa[10]=ve[cc][2].z; xa[11]=ve[cc][2].w;
        xa[12]=ve[cc][3].x; xa[13]=ve[cc][3].y; xa[14]=ve[cc][3].z; xa[15]=ve[cc][3].w;
        float d[8] = {0,0,0,0,0,0,0,0}, s[8] = {0,0,0,0,0,0,0,0};
#pragma unroll
        for (int j = 0; j < 16; j++)
#pragma unroll
            for (int k = 0; k < 8; k++) {
                d[k] = fmaf(xa[j], ed[j * 8 + k], d[k]);
                s[k] = fmaf(xa[j], es[j * 8 + k], s[k]);
            }
        size_t ob = ((size_t)bt * 64 + cp * 2 + cc) * 8;
        *(float4*)&dco[ob]     = make_float4(d[0], d[1], d[2], d[3]);
        *(float4*)&dco[ob + 4] = make_float4(d[4], d[5], d[6], d[7]);
        *(float4*)&sco[ob]     = make_float4(s[0], s[1], s[2], s[3]);
        *(float4*)&sco[ob + 4] = make_float4(s[4], s[5], s[6], s[7]);
    }
}

// ===========================================================================
// Forward truncated DFT, BOTH levels in one launch (grid.z = 32)
// ===========================================================================
__global__ __launch_bounds__(256) void dftfwd_kernel(
    const float* __restrict__ zd0, const float* __restrict__ zs0,
    const float* __restrict__ zd1, const float* __restrict__ zs1,
    const float* __restrict__ bF0, const float* __restrict__ bF1,
    float* __restrict__ out_part)
{
    __shared__ float As[16][128];
    __shared__ float Bs[16][64];
    const int tid = threadIdx.x;
    const int g = blockIdx.z;
    const float* z;
    const float* bF;
    int n, kchunk;
    if (g < 16) { z = (g < 8) ? zd0 : zs0; bF = bF0; n = 2048; kchunk = 256; }
    else        { z = (g < 24) ? zd1 : zs1; bF = bF1; n = 1024; kchunk = 128; }
    z += (size_t)(g & 7) * n * 512;
    const int i0 = blockIdx.x * 128;
    const int tbase = blockIdx.y * kchunk;

    const int tx = tid & 15;
    const int ty = tid >> 4;

    float acc[8][4];
#pragma unroll
    for (int i = 0; i < 8; i++)
#pragma unroll
        for (int j = 0; j < 4; j++) acc[i][j] = 0.f;

    for (int tc = 0; tc < kchunk; tc += 16) {
#pragma unroll
        for (int p = 0; p < 2; p++) {
            int tr = (tid >> 5) + p * 8;
            int ic = (tid & 31) * 4;
            *(float4*)&As[tr][ic] = *(const float4*)&z[(size_t)(tbase + tc + tr) * 512 + i0 + ic];
        }
        {
            int tr = tid >> 4;
            int mc = (tid & 15) * 4;
            *(float4*)&Bs[tr][mc] = *(const float4*)&bF[(size_t)(tbase + tc + tr) * 64 + mc];
        }
        __syncthreads();
#pragma unroll
        for (int kk = 0; kk < 16; kk++) {
            float4 a0 = *(const float4*)&As[kk][ty * 8 + 0];
            float4 a1 = *(const float4*)&As[kk][ty * 8 + 4];
            float4 bv = *(const float4*)&Bs[kk][tx * 4];
            float av[8] = {a0.x,a0.y,a0.z,a0.w,a1.x,a1.y,a1.z,a1.w};
            float bb[4] = {bv.x,bv.y,bv.z,bv.w};
#pragma unroll
            for (int i = 0; i < 8; i++)
#pragma unroll
                for (int j = 0; j < 4; j++)
                    acc[i][j] = fmaf(av[i], bb[j], acc[i][j]);
        }
        __syncthreads();
    }
#pragma unroll
    for (int i = 0; i < 8; i++) {
        size_t base = (((size_t)blockIdx.y * 32 + g) * 512 + (i0 + ty * 8 + i)) * 64 + tx * 4;
        float4 o = make_float4(acc[i][0], acc[i][1], acc[i][2], acc[i][3]);
        *(float4*)&out_part[base] = o;
    }
}

__global__ __launch_bounds__(256) void reduce_parts(
    const float* __restrict__ part, float* __restrict__ out, int count, int nparts)
{
    int e = blockIdx.x * 256 + threadIdx.x;
    if (e >= count) return;
    float s = 0.f;
    for (int p = 0; p < nparts; p++) s += part[(size_t)p * count + e];
    out[e] = s;
}

// ===========================================================================
// Mode mixing SPLIT into U and S kernels; i-split 8 (grid 64 x 8).
// Output layout per partial: [slot32][o][m]. U writes slots lev*16+b,
// S writes lev*16+8+b (disjoint; both into the same partial buffer).
// ===========================================================================
__global__ __launch_bounds__(256) void modemix_U(
    const float* __restrict__ zf,
    const float* __restrict__ waR, const float* __restrict__ waI,
    const float* __restrict__ wbR, const float* __restrict__ wbI,
    float* __restrict__ out_part)
{
    __shared__ float zdS[2][8][8][64];
    __shared__ float zsS[2][8][8][64];
    const int x = threadIdx.x & 31;
    const int q = threadIdx.x >> 5;
    const int o = blockIdx.x * 8 + q;
    const int i0 = blockIdx.y * 64;

    float uR[16], uI[16];
#pragma unroll
    for (int b = 0; b < 16; b++) { uR[b]=0.f; uI[b]=0.f; }

    for (int ic = 0; ic < 64; ic += 8) {
        __syncthreads();
        for (int e = threadIdx.x; e < 8192; e += 256) {
            int lev = e >> 12, r = e & 4095;
            int b = r >> 9, rr = r & 511, ii = rr >> 6, xx = rr & 63;
            size_t gidx = ((size_t)b * 512 + (i0 + ic + ii)) * 64 + xx;
            size_t lbase = (size_t)lev * 16 * 512 * 64;
            zdS[lev][b][ii][xx] = zf[lbase + gidx];
            zsS[lev][b][ii][xx] = zf[lbase + 8ull * 512 * 64 + gidx];
        }
        __syncthreads();
#pragma unroll 2
        for (int ii = 0; ii < 8; ii++) {
            int i = i0 + ic + ii;
            size_t wbase = ((size_t)i * 512 + o) * 32 + x;
            float war = waR[wbase], wai = waI[wbase];
            float wbr = wbR[wbase], wbi = wbI[wbase];
#pragma unroll
            for (int lev = 0; lev < 2; lev++)
#pragma unroll
            for (int b = 0; b < 8; b++) {
                int bb = lev * 8 + b;
                float zr = zdS[lev][b][ii][x];
                float zi = -zdS[lev][b][ii][32 + x];
                float sr = zsS[lev][b][ii][x];
                float si = -zsS[lev][b][ii][32 + x];
                uR[bb] = fmaf(zr, war, uR[bb]); uR[bb] = fmaf(-zi, wai, uR[bb]);
                uR[bb] = fmaf(sr, wbr, uR[bb]); uR[bb] = fmaf(-si, wbi, uR[bb]);
                uI[bb] = fmaf(zr, wai, uI[bb]); uI[bb] = fmaf(zi, war, uI[bb]);
                uI[bb] = fmaf(sr, wbi, uI[bb]); uI[bb] = fmaf(si, wbr, uI[bb]);
            }
        }
    }
#pragma unroll
    for (int bb = 0; bb < 16; bb++) {
        int lev = bb >> 3, b = bb & 7;
        size_t slotU = (size_t)blockIdx.y * 32 + lev * 16 + b;
        out_part[(slotU * 512 + o) * 64 + x]      = uR[bb];
        out_part[(slotU * 512 + o) * 64 + 32 + x] = uI[bb];
    }
}

__global__ __launch_bounds__(256) void modemix_S(
    const float* __restrict__ zf,
    const float* __restrict__ wcR, const float* __restrict__ wcI,
    float* __restrict__ out_part)
{
    __shared__ float zdS[2][8][8][64];
    const int x = threadIdx.x & 31;
    const int q = threadIdx.x >> 5;
    const int o = blockIdx.x * 8 + q;
    const int i0 = blockIdx.y * 64;

    float sR[16], sI[16];
#pragma unroll
    for (int b = 0; b < 16; b++) { sR[b]=0.f; sI[b]=0.f; }

    for (int ic = 0; ic < 64; ic += 8) {
        __syncthreads();
        for (int e = threadIdx.x; e < 8192; e += 256) {
            int lev = e >> 12, r = e & 4095;
            int b = r >> 9, rr = r & 511, ii = rr >> 6, xx = rr & 63;
            size_t gidx = ((size_t)b * 512 + (i0 + ic + ii)) * 64 + xx;
            size_t lbase = (size_t)lev * 16 * 512 * 64;
            zdS[lev][b][ii][xx] = zf[lbase + gidx];
        }
        __syncthreads();
#pragma unroll 2
        for (int ii = 0; ii < 8; ii++) {
            int i = i0 + ic + ii;
            size_t wbase = ((size_t)i * 512 + o) * 32 + x;
            float wcr = wcR[wbase], wci = wcI[wbase];
#pragma unroll
            for (int lev = 0; lev < 2; lev++)
#pragma unroll
            for (int b = 0; b < 8; b++) {
                int bb = lev * 8 + b;
                float zr = zdS[lev][b][ii][x];
                float zi = -zdS[lev][b][ii][32 + x];
                sR[bb] = fmaf(zr, wcr, sR[bb]); sR[bb] = fmaf(-zi, wci, sR[bb]);
                sI[bb] = fmaf(zr, wci, sI[bb]); sI[bb] = fmaf(zi, wcr, sI[bb]);
            }
        }
    }
#pragma unroll
    for (int bb = 0; bb < 16; bb++) {
        int lev = bb >> 3, b = bb & 7;
        size_t slotS = (size_t)blockIdx.y * 32 + lev * 16 + 8 + b;
        out_part[(slotS * 512 + o) * 64 + x]      = sR[bb];
        out_part[(slotS * 512 + o) * 64 + 32 + x] = sI[bb];
    }
}

// ===========================================================================
// Recon with fused t0 (level 1), 2 channels/thread
// ===========================================================================
__global__ __launch_bounds__(256) void recon_t0_kernel(
    const float* __restrict__ cur, const float* __restrict__ us,
    const float* __restrict__ ud, const float* __restrict__ rc_e,
    const float* __restrict__ rc_o, const float* __restrict__ t0w,
    const float* __restrict__ t0b, float* __restrict__ out, int n2)
{
    __shared__ float re[128], ro[128], w[64], bb[8];
    if (threadIdx.x < 128) { re[threadIdx.x] = rc_e[threadIdx.x]; ro[threadIdx.x] = rc_o[threadIdx.x]; }
    if (threadIdx.x < 64)  w[threadIdx.x] = t0w[threadIdx.x];
    if (threadIdx.x >= 64 && threadIdx.x < 72) bb[threadIdx.x - 64] = t0b[threadIdx.x - 64];
    __syncthreads();
    int idx = blockIdx.x * 256 + threadIdx.x;
    int total = 8 * n2 * 32;
    if (idx >= total) return;
    int cp = idx & 31;
    int bt = idx >> 5;

    float4 vc[2][2], vu[2][2], vd[2][2];
#pragma unroll
    for (int cc = 0; cc < 2; cc++) {
        size_t base = ((size_t)bt * 64 + cp * 2 + cc) * 8;
        vc[cc][0] = *(const float4*)(cur + base); vc[cc][1] = *(const float4*)(cur + base + 4);
        vu[cc][0] = *(const float4*)(us + base);  vu[cc][1] = *(const float4*)(us + base + 4);
        vd[cc][0] = *(const float4*)(ud + base);  vd[cc][1] = *(const float4*)(ud + base + 4);
    }
#pragma unroll
    for (int cc = 0; cc < 2; cc++) {
        int c = cp * 2 + cc;
        float sv[8] = {vc[cc][0].x,vc[cc][0].y,vc[cc][0].z,vc[cc][0].w,
                       vc[cc][1].x,vc[cc][1].y,vc[cc][1].z,vc[cc][1].w};
        float uu[8] = {vu[cc][0].x,vu[cc][0].y,vu[cc][0].z,vu[cc][0].w,
                       vu[cc][1].x,vu[cc][1].y,vu[cc][1].z,vu[cc][1].w};
        float v[16];
        v[8]=vd[cc][0].x; v[9]=vd[cc][0].y; v[10]=vd[cc][0].z; v[11]=vd[cc][0].w;
        v[12]=vd[cc][1].x; v[13]=vd[cc][1].y; v[14]=vd[cc][1].z; v[15]=vd[cc][1].w;
#pragma unroll
        for (int k = 0; k < 8; k++) {
            float t = bb[k];
#pragma unroll
            for (int j = 0; j < 8; j++) t = fmaf(sv[j], w[j * 8 + k], t);
            v[k] = t + uu[k];
        }
        float xe[8] = {0,0,0,0,0,0,0,0}, xo[8] = {0,0,0,0,0,0,0,0};
#pragma unroll
        for (int j = 0; j < 16; j++)
#pragma unroll
            for (int k = 0; k < 8; k++) {
                xe[k] = fmaf(v[j], re[j * 8 + k], xe[k]);
                xo[k] = fmaf(v[j], ro[j * 8 + k], xo[k]);
            }
        float* pe = out + ((size_t)(128 * bt + c)) * 8;
        *(float4*)(pe + 0)   = make_float4(xe[0], xe[1], xe[2], xe[3]);
        *(float4*)(pe + 4)   = make_float4(xe[4], xe[5], xe[6], xe[7]);
        *(float4*)(pe + 512) = make_float4(xo[0], xo[1], xo[2], xo[3]);
        *(float4*)(pe + 516) = make_float4(xo[4], xo[5], xo[6], xo[7]);
    }
}

// Recon (level 0), 2 channels/thread
__global__ __launch_bounds__(256) void recon_kernel(
    const float* __restrict__ cur, const float* __restrict__ us,
    const float* __restrict__ ud, const float* __restrict__ rc_e,
    const float* __restrict__ rc_o, float* __restrict__ out, int n2)
{
    __shared__ float re[128], ro[128];
    if (threadIdx.x < 128) { re[threadIdx.x] = rc_e[threadIdx.x]; ro[threadIdx.x] = rc_o[threadIdx.x]; }
    __syncthreads();
    int idx = blockIdx.x * 256 + threadIdx.x;
    int total = 8 * n2 * 32;
    if (idx >= total) return;
    int cp = idx & 31;
    int bt = idx >> 5;

    float4 vc[2][2], vu[2][2], vd[2][2];
#pragma unroll
    for (int cc = 0; cc < 2; cc++) {
        size_t base = ((size_t)bt * 64 + cp * 2 + cc) * 8;
        vc[cc][0] = *(const float4*)(cur + base); vc[cc][1] = *(const float4*)(cur + base + 4);
        vu[cc][0] = *(const float4*)(us + base);  vu[cc][1] = *(const float4*)(us + base + 4);
        vd[cc][0] = *(const float4*)(ud + base);  vd[cc][1] = *(const float4*)(ud + base + 4);
    }
#pragma unroll
    for (int cc = 0; cc < 2; cc++) {
        int c = cp * 2 + cc;
        float v[16];
        v[0]=vc[cc][0].x+vu[cc][0].x; v[1]=vc[cc][0].y+vu[cc][0].y;
        v[2]=vc[cc][0].z+vu[cc][0].z; v[3]=vc[cc][0].w+vu[cc][0].w;
        v[4]=vc[cc][1].x+vu[cc][1].x; v[5]=vc[cc][1].y+vu[cc][1].y;
        v[6]=vc[cc][1].z+vu[cc][1].z; v[7]=vc[cc][1].w+vu[cc][1].w;
        v[8]=vd[cc][0].x; v[9]=vd[cc][0].y; v[10]=vd[cc][0].z; v[11]=vd[cc][0].w;
        v[12]=vd[cc][1].x; v[13]=vd[cc][1].y; v[14]=vd[cc][1].z; v[15]=vd[cc][1].w;
        float xe[8] = {0,0,0,0,0,0,0,0}, xo[8] = {0,0,0,0,0,0,0,0};
#pragma unroll
        for (int j = 0; j < 16; j++)
#pragma unroll
            for (int k = 0; k < 8; k++) {
                xe[k] = fmaf(v[j], re[j * 8 + k], xe[k]);
                xo[k] = fmaf(v[j], ro[j * 8 + k], xo[k]);
            }
        float* pe = out + ((size_t)(128 * bt + c)) * 8;
        *(float4*)(pe + 0)   = make_float4(xe[0], xe[1], xe[2], xe[3]);
        *(float4*)(pe + 4)   = make_float4(xe[4], xe[5], xe[6], xe[7]);
        *(float4*)(pe + 512) = make_float4(xo[0], xo[1], xo[2], xo[3]);
        *(float4*)(pe + 516) = make_float4(xo[4], xo[5], xo[6], xo[7]);
    }
}

// ===========================================================================
// Host orchestration
// ===========================================================================
#define SYM(p, s) do { void* _t; cudaGetSymbolAddress(&_t, s); p = (decltype(p))_t; } while (0)

extern "C" void kernel_launch(void* const* d_in, const int* in_sizes, int n_in,
                              void* d_out, int out_size)
{
    const float* x        = (const float*)d_in[0];
    const float* lin_in_w = (const float*)d_in[1];
    const float* lin_in_b = (const float*)d_in[2];
    const float* lin_out_w= (const float*)d_in[3];
    const float* lin_out_b= (const float*)d_in[4];
    const float* t0_w     = (const float*)d_in[5];
    const float* t0_b     = (const float*)d_in[6];
    const float* wA_re    = (const float*)d_in[7];
    const float* wA_im    = (const float*)d_in[8];
    const float* wB_re    = (const float*)d_in[9];
    const float* wB_im    = (const float*)d_in[10];
    const float* wC_re    = (const float*)d_in[11];
    const float* wC_im    = (const float*)d_in[12];
    const float* ec_s     = (const float*)d_in[13];
    const float* ec_d     = (const float*)d_in[14];
    const float* rc_e     = (const float*)d_in[15];
    const float* rc_o     = (const float*)d_in[16];

    float *pz, *pd0, *ps0, *pd1, *ps1, *pUS0, *pUS1;
    float *prec1, *prec0, *pzfp, *pzf, *pmixp, *pmix;
    float *pbF2, *pbI2, *pbF1, *pbI1, *pbt32;
    SYM(pz, g_z); SYM(pd0, g_d0); SYM(ps0, g_s0);
    SYM(pd1, g_d1); SYM(ps1, g_s1);
    SYM(pUS0, g_US0); SYM(pUS1, g_US1);
    SYM(prec1, g_rec1); SYM(prec0, g_rec0);
    SYM(pzfp, g_zf_part); SYM(pzf, g_zf);
    SYM(pmixp, g_mixp); SYM(pmix, g_mix);
    SYM(pbF2, g_bF2048); SYM(pbI2, g_bI2048); SYM(pbF1, g_bF1024); SYM(pbI1, g_bI1024);
    SYM(pbt32, g_bt32);

    const int ZFCOUNT  = 32 * 512 * 64;
    const int MIXCOUNT = 32 * 512 * 64;

    // 0) basis tables
    basis_kernel<<<512, 256>>>();

    // 1) lin_in via tf32 mma
    wgt_tf32<<<dim3(16, 16), dim3(32, 8)>>>(lin_in_w, pbt32);
    gemm_tf32<<<dim3(4, 256), 256>>>(x, pbt32, lin_in_b, pz);

    // 2) both encodes
    encode_kernel<<<(8 * 2048 * 32) / 256, 256>>>(pz, ec_d, ec_s, pd0, ps0, 2048);
    encode_kernel<<<(8 * 1024 * 32) / 256, 256>>>(ps0, ec_d, ec_s, pd1, ps1, 1024);

    // 3) forward DFTs, both levels, one launch
    dftfwd_kernel<<<dim3(4, 8, 32), 256>>>(pd0, ps0, pd1, ps1, pbF2, pbF1, pzfp);
    reduce_parts<<<(ZFCOUNT + 255) / 256, 256>>>(pzfp, pzf, ZFCOUNT, 8);

    // 4) modemix split into U and S kernels, i-split 8, disjoint slots
    modemix_U<<<dim3(64, 8), 256>>>(pzf, wA_re, wA_im, wB_re, wB_im, pmixp);
    modemix_S<<<dim3(64, 8), 256>>>(pzf, wC_re, wC_im, pmixp);
    reduce_parts<<<(MIXCOUNT + 255) / 256, 256>>>(pmixp, pmix, MIXCOUNT, 8);

    // 5) inverse DFTs via tf32 mma (z-batched)
    invdft_tf32<<<dim3(4, 16, 16), 256>>>(pbI2, pmix, pUS0, 2048);
    invdft_tf32<<<dim3(4, 8, 16), 256>>>(pbI1, pmix + 16ull * 512 * 64, pUS1, 1024);

    // 6) reconstruction (t0 fused into level-1 recon)
    recon_t0_kernel<<<(8 * 1024 * 32) / 256, 256>>>(
        ps1, pUS1 + 8ull * 1024 * 512, pUS1, rc_e, rc_o, t0_w, t0_b, prec1, 1024);
    recon_kernel<<<(8 * 2048 * 32) / 256, 256>>>(
        prec1, pUS0 + 8ull * 2048 * 512, pUS0, rc_e, rc_o, prec0, 2048);

    // 7) lin_out via tf32 mma -> d_out
    wgt_tf32<<<dim3(16, 16), dim3(32, 8)>>>(lin_out_w, pbt32);
    gemm_tf32<<<dim3(4, 256), 256>>>(prec0, pbt32, lin_out_b, (float*)d_out);

    (void)in_sizes; (void)n_in; (void)out_size;
}

// round 14
// speedup vs baseline: 1.2222x; 1.1548x over previous
#include <cuda_runtime.h>
#include <cuda_bf16.h>
#include <math.h>
#include <stdint.h>

// Problem constants: B=8, T=4096, H=8, D=64, CK=512, K=8, C=64, MODES=32, L=2

#define DEVBUF __device__ __align__(256)
DEVBUF float g_z   [8ull*4096*512];
DEVBUF float g_d0  [8ull*2048*512];
DEVBUF float g_s0  [8ull*2048*512];
DEVBUF float g_d1  [8ull*1024*512];
DEVBUF float g_s1  [8ull*1024*512];
DEVBUF float g_US0 [16ull*2048*512];   // [0..8) = Ud0 batches, [8..16) = Us0
DEVBUF float g_US1 [16ull*1024*512];   // [0..8) = Ud1, [8..16) = Us1
DEVBUF float g_rec1[8ull*2048*512];
DEVBUF float g_rec0[8ull*4096*512];
DEVBUF float g_zf_part[8ull*32*512*64];
DEVBUF float g_zf     [32ull*512*64];
DEVBUF float g_mixp[8ull*32*512*64];   // modemix partials (i-split 8), [part][slot][o][m]
DEVBUF float g_mix [32ull*512*64];     // [slot][o(512)][m(64)]
DEVBUF float g_bF2048[2048*64];
DEVBUF float g_bI2048[2048*64];        // tf32-prerounded
DEVBUF float g_bF1024[1024*64];
DEVBUF float g_bI1024[1024*64];        // tf32-prerounded
DEVBUF float g_bt32[512ull*512];

// ===========================================================================
// Helpers (sm_80-baseline PTX: mma.sync tf32 / ldmatrix / cp.async)
// ===========================================================================
__device__ __forceinline__ uint32_t smem_u32(const void* p) {
    uint32_t a;
    asm("{ .reg .u64 t; cvta.to.shared.u64 t, %1; cvt.u32.u64 %0, t; }" : "=r"(a) : "l"(p));
    return a;
}
__device__ __forceinline__ void cp16(uint32_t smaddr, const void* g) {
    asm volatile("cp.async.cg.shared.global [%0], [%1], 16;" :: "r"(smaddr), "l"(g));
}
#define CP_COMMIT() asm volatile("cp.async.commit_group;" ::: "memory")
#define CP_WAIT2()  asm volatile("cp.async.wait_group 2;" ::: "memory")

__device__ __forceinline__ void ldsm4(uint32_t* r, uint32_t a) {
    asm volatile("ldmatrix.sync.aligned.m8n8.x4.shared.b16 {%0,%1,%2,%3}, [%4];"
        : "=r"(r[0]), "=r"(r[1]), "=r"(r[2]), "=r"(r[3]) : "r"(a));
}
__device__ __forceinline__ void ldsm2(uint32_t* r, uint32_t a) {
    asm volatile("ldmatrix.sync.aligned.m8n8.x2.shared.b16 {%0,%1}, [%2];"
        : "=r"(r[0]), "=r"(r[1]) : "r"(a));
}
__device__ __forceinline__ void mma_tf32(float* c, const uint32_t* a, const uint32_t* b) {
    asm volatile("mma.sync.aligned.m16n8k8.row.col.f32.tf32.tf32.f32 "
        "{%0,%1,%2,%3}, {%4,%5,%6,%7}, {%8,%9}, {%0,%1,%2,%3};"
        : "+f"(c[0]), "+f"(c[1]), "+f"(c[2]), "+f"(c[3])
        : "r"(a[0]), "r"(a[1]), "r"(a[2]), "r"(a[3]), "r"(b[0]), "r"(b[1]));
}
__device__ __forceinline__ uint32_t cvt_tf32(uint32_t u) {
    uint32_t o;
    float f = __uint_as_float(u);
    asm("cvt.rna.tf32.f32 %0, %1;" : "=r"(o) : "f"(f));
    return o;
}

// ===========================================================================
// tf32 mma GEMM (R6/R8-proven): C[32768,512] = A[32768,512] @ W[512,512]+bias
// ===========================================================================
__global__ __launch_bounds__(256, 2) void gemm_tf32(
    const float* __restrict__ A, const float* __restrict__ Bt,
    const float* __restrict__ bias, float* __restrict__ C)
{
    __shared__ __align__(1024) float sA[3][128 * 16];
    __shared__ __align__(1024) float sB[3][128 * 16];

    const int tid  = threadIdx.x;
    const int wid  = tid >> 5;
    const int lane = tid & 31;
    const int m0 = blockIdx.y * 128;
    const int n0 = blockIdx.x * 128;
    const int wm = (wid >> 1) * 32;
    const int wn = (wid & 1) * 64;

    const uint32_t sA0 = smem_u32(sA);
    const uint32_t sB0 = smem_u32(sB);

    const int r0 = (tid + 0)   >> 2, c0 = (tid + 0)   & 3;
    const int r1 = (tid + 256) >> 2, c1 = (tid + 256) & 3;
    const uint32_t so0 = (uint32_t)(r0 * 64 + ((c0 ^ ((r0 >> 1) & 3)) * 16));
    const uint32_t so1 = (uint32_t)(r1 * 64 + ((c1 ^ ((r1 >> 1) & 3)) * 16));

    auto load_chunk = [&](int it, int s) {
        const int kb = it * 16;
        cp16(sA0 + s * 8192 + so0, A + (size_t)(m0 + r0) * 512 + kb + c0 * 4);
        cp16(sA0 + s * 8192 + so1, A + (size_t)(m0 + r1) * 512 + kb + c1 * 4);
        cp16(sB0 + s * 8192 + so0, Bt + (size_t)(n0 + r0) * 512 + kb + c0 * 4);
        cp16(sB0 + s * 8192 + so1, Bt + (size_t)(n0 + r1) * 512 + kb + c1 * 4);
        CP_COMMIT();
    };

    float acc[2][8][4];
#pragma unroll
    for (int i = 0; i < 2; i++)
#pragma unroll
        for (int j = 0; j < 8; j++)
#pragma unroll
            for (int k = 0; k < 4; k++) acc[i][j][k] = 0.f;

    const int la = lane & 15;
    const int ka = lane >> 4;
    const int lb = lane & 7;
    const int kb8 = (lane >> 3) & 1;

    load_chunk(0, 0);
    load_chunk(1, 1);

    const int NC = 32;
    for (int it = 0; it < NC; it++) {
        const int s = it % 3;
        if (it + 2 < NC) load_chunk(it + 2, (it + 2) % 3);
        else CP_COMMIT();
        CP_WAIT2();
        __syncthreads();

#pragma unroll
        for (int k8 = 0; k8 < 2; k8++) {
            uint32_t afr[2][4];
#pragma unroll
            for (int tm = 0; tm < 2; tm++) {
                int row = wm + tm * 16 + la;
                int k4 = k8 * 2 + ka;
                uint32_t addr = sA0 + s * 8192 + (uint32_t)(row * 64 + ((k4 ^ ((row >> 1) & 3)) * 16));
                ldsm4(afr[tm], addr);
#pragma unroll
                for (int q = 0; q < 4; q++) afr[tm][q] = cvt_tf32(afr[tm][q]);
            }
            uint32_t bfr[8][2];
#pragma unroll
            for (int n8 = 0; n8 < 8; n8++) {
                int row = wn + n8 * 8 + lb;
                int k4 = k8 * 2 + kb8;
                uint32_t addr = sB0 + s * 8192 + (uint32_t)(row * 64 + ((k4 ^ ((row >> 1) & 3)) * 16));
                ldsm2(bfr[n8], addr);
            }
#pragma unroll
            for (int tm = 0; tm < 2; tm++)
#pragma unroll
                for (int n8 = 0; n8 < 8; n8++)
                    mma_tf32(acc[tm][n8], afr[tm], bfr[n8]);
        }
        __syncthreads();
    }

    const int er = lane >> 2;
    const int ec = (lane & 3) * 2;
#pragma unroll
    for (int tm = 0; tm < 2; tm++) {
        const int m = m0 + wm + tm * 16 + er;
#pragma unroll
        for (int n8 = 0; n8 < 8; n8++) {
            const int n = n0 + wn + n8 * 8 + ec;
            const float b0 = bias[n], b1 = bias[n + 1];
            float2 v0 = make_float2(acc[tm][n8][0] + b0, acc[tm][n8][1] + b1);
            float2 v1 = make_float2(acc[tm][n8][2] + b0, acc[tm][n8][3] + b1);
            *(float2*)&C[(size_t)m * 512 + n]       = v0;
            *(float2*)&C[(size_t)(m + 8) * 512 + n] = v1;
        }
    }
}

__global__ void wgt_tf32(const float* __restrict__ W, float* __restrict__ Bt) {
    __shared__ float t[32][33];
    const int n0 = blockIdx.x * 32, k0 = blockIdx.y * 32;
    for (int i = threadIdx.y; i < 32; i += 8)
        t[i][threadIdx.x] = W[(size_t)(k0 + i) * 512 + n0 + threadIdx.x];
    __syncthreads();
    for (int i = threadIdx.y; i < 32; i += 8) {
        uint32_t v = cvt_tf32(__float_as_uint(t[threadIdx.x][i]));
        Bt[(size_t)(n0 + i) * 512 + k0 + threadIdx.x] = __uint_as_float(v);
    }
}

// ===========================================================================
// Inverse-DFT via tf32 mma: C[z][t][i] = bI[t][m] @ mixT[z][i][m]
// ===========================================================================
__global__ __launch_bounds__(256, 2) void invdft_tf32(
    const float* __restrict__ Abi, const float* __restrict__ Bm,
    float* __restrict__ C, int n2)
{
    __shared__ __align__(1024) float sA[3][128 * 16];
    __shared__ __align__(1024) float sB[3][128 * 16];

    const int tid  = threadIdx.x;
    const int wid  = tid >> 5;
    const int lane = tid & 31;
    const int m0 = blockIdx.y * 128;
    const int n0 = blockIdx.x * 128;
    const int z  = blockIdx.z;
    Bm += (size_t)z * 512 * 64;
    C  += (size_t)z * n2 * 512;
    const int wm = (wid >> 1) * 32;
    const int wn = (wid & 1) * 64;

    const uint32_t sA0 = smem_u32(sA);
    const uint32_t sB0 = smem_u32(sB);

    const int r0 = tid >> 2, c0 = tid & 3;
    const int r1 = r0 + 64;
    const uint32_t so0 = (uint32_t)(r0 * 64 + ((c0 ^ ((r0 >> 1) & 3)) * 16));
    const uint32_t so1 = (uint32_t)(r1 * 64 + ((c0 ^ ((r1 >> 1) & 3)) * 16));

    auto load_chunk = [&](int it, int s) {
        const int kb = it * 16;
        cp16(sA0 + s * 8192 + so0, Abi + (size_t)(m0 + r0) * 64 + kb + c0 * 4);
        cp16(sA0 + s * 8192 + so1, Abi + (size_t)(m0 + r1) * 64 + kb + c0 * 4);
        cp16(sB0 + s * 8192 + so0, Bm + (size_t)(n0 + r0) * 64 + kb + c0 * 4);
        cp16(sB0 + s * 8192 + so1, Bm + (size_t)(n0 + r1) * 64 + kb + c0 * 4);
        CP_COMMIT();
    };

    float acc[2][8][4];
#pragma unroll
    for (int i = 0; i < 2; i++)
#pragma unroll
        for (int j = 0; j < 8; j++)
#pragma unroll
            for (int k = 0; k < 4; k++) acc[i][j][k] = 0.f;

    const int la = lane & 15;
    const int ka = lane >> 4;
    const int b_r = wn + (lane & 7) + ((lane & 16) ? 8 : 0);
    const int b_u = (lane >> 3) & 1;

    load_chunk(0, 0);
    load_chunk(1, 1);

    const int NC = 4;
    for (int it = 0; it < NC; it++) {
        const int s = it % 3;
        if (it + 2 < NC) load_chunk(it + 2, (it + 2) % 3);
        else CP_COMMIT();
        CP_WAIT2();
        __syncthreads();

#pragma unroll
        for (int k8 = 0; k8 < 2; k8++) {
            uint32_t afr[2][4];
#pragma unroll
            for (int tm = 0; tm < 2; tm++) {
                int row = wm + tm * 16 + la;
                int k4 = k8 * 2 + ka;
                uint32_t addr = sA0 + s * 8192 + (uint32_t)(row * 64 + ((k4 ^ ((row >> 1) & 3)) * 16));
                ldsm4(afr[tm], addr);
            }
            uint32_t bfr[4][4];
#pragma unroll
            for (int p = 0; p < 4; p++) {
                int row = b_r + p * 16;
                int k4 = k8 * 2 + b_u;
                uint32_t addr = sB0 + s * 8192 + (uint32_t)(row * 64 + ((k4 ^ ((row >> 1) & 3)) * 16));
                ldsm4(bfr[p], addr);
#pragma unroll
                for (int q = 0; q < 4; q++) bfr[p][q] = cvt_tf32(bfr[p][q]);
            }
#pragma unroll
            for (int tm = 0; tm < 2; tm++)
#pragma unroll
                for (int p = 0; p < 4; p++) {
                    mma_tf32(acc[tm][p * 2 + 0], afr[tm], &bfr[p][0]);
                    mma_tf32(acc[tm][p * 2 + 1], afr[tm], &bfr[p][2]);
                }
        }
        __syncthreads();
    }

    const int er = lane >> 2;
    const int ec = (lane & 3) * 2;
#pragma unroll
    for (int tm = 0; tm < 2; tm++) {
        const int m = m0 + wm + tm * 16 + er;
#pragma unroll
        for (int n8 = 0; n8 < 8; n8++) {
            const int n = n0 + wn + n8 * 8 + ec;
            *(float2*)&C[(size_t)m * 512 + n]       = make_float2(acc[tm][n8][0], acc[tm][n8][1]);
            *(float2*)&C[(size_t)(m + 8) * 512 + n] = make_float2(acc[tm][n8][2], acc[tm][n8][3]);
        }
    }
}

// ===========================================================================
// Basis tables (bI pre-rounded to tf32)
// ===========================================================================
__device__ __forceinline__ void fill_tables(float* bF, float* bI, int t, int m, int n) {
    int x = (m < 32) ? m : (m - 32);
    long r = ((long)t * (long)x) % (long)n;
    double ang = 6.283185307179586476925286766559 * (double)r / (double)n;
    double c = cos(ang), s = sin(ang);
    bF[t*64 + m] = (m < 32) ? (float)c : (float)s;
    float vi;
    if (m == 0)          vi = 1.0f / (float)n;
    else if (m < 32)     vi = (float)(2.0 * c / (double)n);
    else if (m == 32)    vi = 0.0f;
    else                 vi = (float)(-2.0 * s / (double)n);
    bI[t*64 + m] = __uint_as_float(cvt_tf32(__float_as_uint(vi)));
}

__global__ __launch_bounds__(256) void basis_kernel() {
    int idx = blockIdx.x * 256 + threadIdx.x;
    if (idx < 2048*64) {
        int t = idx >> 6, m = idx & 63;
        fill_tables(g_bF2048, g_bI2048, t, m, 2048);
    }
    if (idx < 1024*64) {
        int t = idx >> 6, m = idx & 63;
        fill_tables(g_bF1024, g_bI1024, t, m, 1024);
    }
}

// ===========================================================================
// Encode: 2 channels per thread, float4 loads/stores (high MLP)
// ===========================================================================
__global__ __launch_bounds__(256) void encode_kernel(
    const float* __restrict__ cur, const float* __restrict__ ec_d,
    const float* __restrict__ ec_s, float* __restrict__ dco,
    float* __restrict__ sco, int n2)
{
    __shared__ float ed[128], es[128];
    if (threadIdx.x < 128) { ed[threadIdx.x] = ec_d[threadIdx.x]; es[threadIdx.x] = ec_s[threadIdx.x]; }
    __syncthreads();
    int idx = blockIdx.x * 256 + threadIdx.x;
    int total = 8 * n2 * 32;
    if (idx >= total) return;
    int cp = idx & 31;
    int bt = idx >> 5;
    const float* pe = cur + ((size_t)(128 * bt) + cp * 2) * 8;

    float4 ve[2][4];
#pragma unroll
    for (int cc = 0; cc < 2; cc++) {
        const float* p = pe + cc * 8;
        ve[cc][0] = *(const float4*)(p + 0);
        ve[cc][1] = *(const float4*)(p + 4);
        ve[cc][2] = *(const float4*)(p + 512);
        ve[cc][3] = *(const float4*)(p + 516);
    }
#pragma unroll
    for (int cc = 0; cc < 2; cc++) {
        float xa[16];
        xa[0]=ve[cc][0].x; xa[1]=ve[cc][0].y; xa[2]=ve[cc][0].z; xa[3]=ve[cc][0].w;
        xa[4]=ve[cc][1].x; xa[5]=ve[cc][1].y; xa[6]=ve[cc][1].z; xa[7]=ve[cc][1].w;
        xa[8]=ve[cc][2].x; xa[9]=ve[cc][2].y; xa[10]=ve[cc][2].z; xa[11]=ve[cc][2].w;
        xa[12]=ve[cc][3].x; xa[13]=ve[cc][3].y; xa[14]=ve[cc][3].z; xa[15]=ve[cc][3].w;
        float d[8] = {0,0,0,0,0,0,0,0}, s[8] = {0,0,0,0,0,0,0,0};
#pragma unroll
        for (int j = 0; j < 16; j++)
#pragma unroll
            for (int k = 0; k < 8; k++) {
                d[k] = fmaf(xa[j], ed[j * 8 + k], d[k]);
                s[k] = fmaf(xa[j], es[j * 8 + k], s[k]);
            }
        size_t ob = ((size_t)bt * 64 + cp * 2 + cc) * 8;
        *(float4*)&dco[ob]     = make_float4(d[0], d[1], d[2], d[3]);
        *(float4*)&dco[ob + 4] = make_float4(d[4], d[5], d[6], d[7]);
        *(float4*)&sco[ob]     = make_float4(s[0], s[1], s[2], s[3]);
        *(float4*)&sco[ob + 4] = make_float4(s[4], s[5], s[6], s[7]);
    }
}

// ===========================================================================
// Forward truncated DFT, BOTH levels in one launch (grid.z = 32)
// ===========================================================================
__global__ __launch_bounds__(256) void dftfwd_kernel(
    const float* __restrict__ zd0, const float* __restrict__ zs0,
    const float* __restrict__ zd1, const float* __restrict__ zs1,
    const float* __restrict__ bF0, const float* __restrict__ bF1,
    float* __restrict__ out_part)
{
    __shared__ float As[16][128];
    __shared__ float Bs[16][64];
    const int tid = threadIdx.x;
    const int g = blockIdx.z;
    const float* z;
    const float* bF;
    int n, kchunk;
    if (g < 16) { z = (g < 8) ? zd0 : zs0; bF = bF0; n = 2048; kchunk = 256; }
    else        { z = (g < 24) ? zd1 : zs1; bF = bF1; n = 1024; kchunk = 128; }
    z += (size_t)(g & 7) * n * 512;
    const int i0 = blockIdx.x * 128;
    const int tbase = blockIdx.y * kchunk;

    const int tx = tid & 15;
    const int ty = tid >> 4;

    float acc[8][4];
#pragma unroll
    for (int i = 0; i < 8; i++)
#pragma unroll
        for (int j = 0; j < 4; j++) acc[i][j] = 0.f;

    for (int tc = 0; tc < kchunk; tc += 16) {
#pragma unroll
        for (int p = 0; p < 2; p++) {
            int tr = (tid >> 5) + p * 8;
            int ic = (tid & 31) * 4;
            *(float4*)&As[tr][ic] = *(const float4*)&z[(size_t)(tbase + tc + tr) * 512 + i0 + ic];
        }
        {
            int tr = tid >> 4;
            int mc = (tid & 15) * 4;
            *(float4*)&Bs[tr][mc] = *(const float4*)&bF[(size_t)(tbase + tc + tr) * 64 + mc];
        }
        __syncthreads();
#pragma unroll
        for (int kk = 0; kk < 16; kk++) {
            float4 a0 = *(const float4*)&As[kk][ty * 8 + 0];
            float4 a1 = *(const float4*)&As[kk][ty * 8 + 4];
            float4 bv = *(const float4*)&Bs[kk][tx * 4];
            float av[8] = {a0.x,a0.y,a0.z,a0.w,a1.x,a1.y,a1.z,a1.w};
            float bb[4] = {bv.x,bv.y,bv.z,bv.w};
#pragma unroll
            for (int i = 0; i < 8; i++)
#pragma unroll
                for (int j = 0; j < 4; j++)
                    acc[i][j] = fmaf(av[i], bb[j], acc[i][j]);
        }
        __syncthreads();
    }
#pragma unroll
    for (int i = 0; i < 8; i++) {
        size_t base = (((size_t)blockIdx.y * 32 + g) * 512 + (i0 + ty * 8 + i)) * 64 + tx * 4;
        float4 o = make_float4(acc[i][0], acc[i][1], acc[i][2], acc[i][3]);
        *(float4*)&out_part[base] = o;
    }
}

__global__ __launch_bounds__(256) void reduce_parts(
    const float* __restrict__ part, float* __restrict__ out, int count, int nparts)
{
    int e = blockIdx.x * 256 + threadIdx.x;
    if (e >= count) return;
    float s = 0.f;
    for (int p = 0; p < nparts; p++) s += part[(size_t)p * count + e];
    out[e] = s;
}

// ===========================================================================
// Mode mixing SPLIT U/S, i-split 8, 2 o-values per warp, vectorized z smem.
// U: zS float4 {zd_re, zd_im_raw, zs_re, zs_im_raw}; S: float2 {zd_re, zd_im_raw}.
// Grid (32, 8): blockIdx.x -> 16 o's per CTA (2 per warp).
// ===========================================================================
__global__ __launch_bounds__(256) void modemix_U(
    const float* __restrict__ zf,
    const float* __restrict__ waR, const float* __restrict__ waI,
    const float* __restrict__ wbR, const float* __restrict__ wbI,
    float* __restrict__ out_part)
{
    __shared__ float4 zS[2][8][8][32];
    const int x = threadIdx.x & 31;
    const int q = threadIdx.x >> 5;
    const int o0 = blockIdx.x * 16 + q * 2;
    const int i0 = blockIdx.y * 64;

    float uR[2][16], uI[2][16];
#pragma unroll
    for (int oo = 0; oo < 2; oo++)
#pragma unroll
        for (int b = 0; b < 16; b++) { uR[oo][b]=0.f; uI[oo][b]=0.f; }

    for (int ic = 0; ic < 64; ic += 8) {
        __syncthreads();
        for (int e = threadIdx.x; e < 4096; e += 256) {
            int lev = e >> 11, r = e & 2047;
            int b = r >> 8, rr = r & 255, ii = rr >> 5, xx = rr & 31;
            size_t gidx = ((size_t)b * 512 + (i0 + ic + ii)) * 64;
            size_t lbase = (size_t)lev * 16 * 512 * 64;
            size_t sofs  = 8ull * 512 * 64;
            zS[lev][b][ii][xx] = make_float4(
                zf[lbase + gidx + xx],        zf[lbase + gidx + 32 + xx],
                zf[lbase + sofs + gidx + xx], zf[lbase + sofs + gidx + 32 + xx]);
        }
        __syncthreads();
#pragma unroll 2
        for (int ii = 0; ii < 8; ii++) {
            int i = i0 + ic + ii;
            float war[2], wai[2], wbr[2], wbi[2];
#pragma unroll
            for (int oo = 0; oo < 2; oo++) {
                size_t wbase = ((size_t)i * 512 + o0 + oo) * 32 + x;
                war[oo] = waR[wbase]; wai[oo] = waI[wbase];
                wbr[oo] = wbR[wbase]; wbi[oo] = wbI[wbase];
            }
#pragma unroll
            for (int lev = 0; lev < 2; lev++)
#pragma unroll
            for (int b = 0; b < 8; b++) {
                int bb = lev * 8 + b;
                float4 zv = zS[lev][b][ii][x];
                float zr = zv.x, zi = -zv.y, sr = zv.z, si = -zv.w;
#pragma unroll
                for (int oo = 0; oo < 2; oo++) {
                    uR[oo][bb] = fmaf(zr, war[oo], uR[oo][bb]); uR[oo][bb] = fmaf(-zi, wai[oo], uR[oo][bb]);
                    uR[oo][bb] = fmaf(sr, wbr[oo], uR[oo][bb]); uR[oo][bb] = fmaf(-si, wbi[oo], uR[oo][bb]);
                    uI[oo][bb] = fmaf(zr, wai[oo], uI[oo][bb]); uI[oo][bb] = fmaf(zi, war[oo], uI[oo][bb]);
                    uI[oo][bb] = fmaf(sr, wbi[oo], uI[oo][bb]); uI[oo][bb] = fmaf(si, wbr[oo], uI[oo][bb]);
                }
            }
        }
    }
#pragma unroll
    for (int bb = 0; bb < 16; bb++) {
        int lev = bb >> 3, b = bb & 7;
        size_t slotU = (size_t)blockIdx.y * 32 + lev * 16 + b;
#pragma unroll
        for (int oo = 0; oo < 2; oo++) {
            out_part[(slotU * 512 + o0 + oo) * 64 + x]      = uR[oo][bb];
            out_part[(slotU * 512 + o0 + oo) * 64 + 32 + x] = uI[oo][bb];
        }
    }
}

__global__ __launch_bounds__(256) void modemix_S(
    const float* __restrict__ zf,
    const float* __restrict__ wcR, const float* __restrict__ wcI,
    float* __restrict__ out_part)
{
    __shared__ float2 zS[2][8][8][32];
    const int x = threadIdx.x & 31;
    const int q = threadIdx.x >> 5;
    const int o0 = blockIdx.x * 16 + q * 2;
    const int i0 = blockIdx.y * 64;

    float sR[2][16], sI[2][16];
#pragma unroll
    for (int oo = 0; oo < 2; oo++)
#pragma unroll
        for (int b = 0; b < 16; b++) { sR[oo][b]=0.f; sI[oo][b]=0.f; }

    for (int ic = 0; ic < 64; ic += 8) {
        __syncthreads();
        for (int e = threadIdx.x; e < 4096; e += 256) {
            int lev = e >> 11, r = e & 2047;
            int b = r >> 8, rr = r & 255, ii = rr >> 5, xx = rr & 31;
            size_t gidx = ((size_t)b * 512 + (i0 + ic + ii)) * 64;
            size_t lbase = (size_t)lev * 16 * 512 * 64;
            zS[lev][b][ii][xx] = make_float2(zf[lbase + gidx + xx], zf[lbase + gidx + 32 + xx]);
        }
        __syncthreads();
#pragma unroll 2
        for (int ii = 0; ii < 8; ii++) {
            int i = i0 + ic + ii;
            float wcr[2], wci[2];
#pragma unroll
            for (int oo = 0; oo < 2; oo++) {
                size_t wbase = ((size_t)i * 512 + o0 + oo) * 32 + x;
                wcr[oo] = wcR[wbase]; wci[oo] = wcI[wbase];
            }
#pragma unroll
            for (int lev = 0; lev < 2; lev++)
#pragma unroll
            for (int b = 0; b < 8; b++) {
                int bb = lev * 8 + b;
                float2 zv = zS[lev][b][ii][x];
                float zr = zv.x, zi = -zv.y;
#pragma unroll
                for (int oo = 0; oo < 2; oo++) {
                    sR[oo][bb] = fmaf(zr, wcr[oo], sR[oo][bb]); sR[oo][bb] = fmaf(-zi, wci[oo], sR[oo][bb]);
                    sI[oo][bb] = fmaf(zr, wci[oo], sI[oo][bb]); sI[oo][bb] = fmaf(zi, wcr[oo], sI[oo][bb]);
                }
            }
        }
    }
#pragma unroll
    for (int bb = 0; bb < 16; bb++) {
        int lev = bb >> 3, b = bb & 7;
        size_t slotS = (size_t)blockIdx.y * 32 + lev * 16 + 8 + b;
#pragma unroll
        for (int oo = 0; oo < 2; oo++) {
            out_part[(slotS * 512 + o0 + oo) * 64 + x]      = sR[oo][bb];
            out_part[(slotS * 512 + o0 + oo) * 64 + 32 + x] = sI[oo][bb];
        }
    }
}

// ===========================================================================
// Recon with fused t0 (level 1), 2 channels/thread
// ===========================================================================
__global__ __launch_bounds__(256) void recon_t0_kernel(
    const float* __restrict__ cur, const float* __restrict__ us,
    const float* __restrict__ ud, const float* __restrict__ rc_e,
    const float* __restrict__ rc_o, const float* __restrict__ t0w,
    const float* __restrict__ t0b, float* __restrict__ out, int n2)
{
    __shared__ float re[128], ro[128], w[64], bb[8];
    if (threadIdx.x < 128) { re[threadIdx.x] = rc_e[threadIdx.x]; ro[threadIdx.x] = rc_o[threadIdx.x]; }
    if (threadIdx.x < 64)  w[threadIdx.x] = t0w[threadIdx.x];
    if (threadIdx.x >= 64 && threadIdx.x < 72) bb[threadIdx.x - 64] = t0b[threadIdx.x - 64];
    __syncthreads();
    int idx = blockIdx.x * 256 + threadIdx.x;
    int total = 8 * n2 * 32;
    if (idx >= total) return;
    int cp = idx & 31;
    int bt = idx >> 5;

    float4 vc[2][2], vu[2][2], vd[2][2];
#pragma unroll
    for (int cc = 0; cc < 2; cc++) {
        size_t base = ((size_t)bt * 64 + cp * 2 + cc) * 8;
        vc[cc][0] = *(const float4*)(cur + base); vc[cc][1] = *(const float4*)(cur + base + 4);
        vu[cc][0] = *(const float4*)(us + base);  vu[cc][1] = *(const float4*)(us + base + 4);
        vd[cc][0] = *(const float4*)(ud + base);  vd[cc][1] = *(const float4*)(ud + base + 4);
    }
#pragma unroll
    for (int cc = 0; cc < 2; cc++) {
        int c = cp * 2 + cc;
        float sv[8] = {vc[cc][0].x,vc[cc][0].y,vc[cc][0].z,vc[cc][0].w,
                       vc[cc][1].x,vc[cc][1].y,vc[cc][1].z,vc[cc][1].w};
        float uu[8] = {vu[cc][0].x,vu[cc][0].y,vu[cc][0].z,vu[cc][0].w,
                       vu[cc][1].x,vu[cc][1].y,vu[cc][1].z,vu[cc][1].w};
        float v[16];
        v[8]=vd[cc][0].x; v[9]=vd[cc][0].y; v[10]=vd[cc][0].z; v[11]=vd[cc][0].w;
        v[12]=vd[cc][1].x; v[13]=vd[cc][1].y; v[14]=vd[cc][1].z; v[15]=vd[cc][1].w;
#pragma unroll
        for (int k = 0; k < 8; k++) {
            float t = bb[k];
#pragma unroll
            for (int j = 0; j < 8; j++) t = fmaf(sv[j], w[j * 8 + k], t);
            v[k] = t + uu[k];
        }
        float xe[8] = {0,0,0,0,0,0,0,0}, xo[8] = {0,0,0,0,0,0,0,0};
#pragma unroll
        for (int j = 0; j < 16; j++)
#pragma unroll
            for (int k = 0; k < 8; k++) {
                xe[k] = fmaf(v[j], re[j * 8 + k], xe[k]);
                xo[k] = fmaf(v[j], ro[j * 8 + k], xo[k]);
            }
        float* pe = out + ((size_t)(128 * bt + c)) * 8;
        *(float4*)(pe + 0)   = make_float4(xe[0], xe[1], xe[2], xe[3]);
        *(float4*)(pe + 4)   = make_float4(xe[4], xe[5], xe[6], xe[7]);
        *(float4*)(pe + 512) = make_float4(xo[0], xo[1], xo[2], xo[3]);
        *(float4*)(pe + 516) = make_float4(xo[4], xo[5], xo[6], xo[7]);
    }
}

// Recon (level 0), 2 channels/thread
__global__ __launch_bounds__(256) void recon_kernel(
    const float* __restrict__ cur, const float* __restrict__ us,
    const float* __restrict__ ud, const float* __restrict__ rc_e,
    const float* __restrict__ rc_o, float* __restrict__ out, int n2)
{
    __shared__ float re[128], ro[128];
    if (threadIdx.x < 128) { re[threadIdx.x] = rc_e[threadIdx.x]; ro[threadIdx.x] = rc_o[threadIdx.x]; }
    __syncthreads();
    int idx = blockIdx.x * 256 + threadIdx.x;
    int total = 8 * n2 * 32;
    if (idx >= total) return;
    int cp = idx & 31;
    int bt = idx >> 5;

    float4 vc[2][2], vu[2][2], vd[2][2];
#pragma unroll
    for (int cc = 0; cc < 2; cc++) {
        size_t base = ((size_t)bt * 64 + cp * 2 + cc) * 8;
        vc[cc][0] = *(const float4*)(cur + base); vc[cc][1] = *(const float4*)(cur + base + 4);
        vu[cc][0] = *(const float4*)(us + base);  vu[cc][1] = *(const float4*)(us + base + 4);
        vd[cc][0] = *(const float4*)(ud + base);  vd[cc][1] = *(const float4*)(ud + base + 4);
    }
#pragma unroll
    for (int cc = 0; cc < 2; cc++) {
        int c = cp * 2 + cc;
        float v[16];
        v[0]=vc[cc][0].x+vu[cc][0].x; v[1]=vc[cc][0].y+vu[cc][0].y;
        v[2]=vc[cc][0].z+vu[cc][0].z; v[3]=vc[cc][0].w+vu[cc][0].w;
        v[4]=vc[cc][1].x+vu[cc][1].x; v[5]=vc[cc][1].y+vu[cc][1].y;
        v[6]=vc[cc][1].z+vu[cc][1].z; v[7]=vc[cc][1].w+vu[cc][1].w;
        v[8]=vd[cc][0].x; v[9]=vd[cc][0].y; v[10]=vd[cc][0].z; v[11]=vd[cc][0].w;
        v[12]=vd[cc][1].x; v[13]=vd[cc][1].y; v[14]=vd[cc][1].z; v[15]=vd[cc][1].w;
        float xe[8] = {0,0,0,0,0,0,0,0}, xo[8] = {0,0,0,0,0,0,0,0};
#pragma unroll
        for (int j = 0; j < 16; j++)
#pragma unroll
            for (int k = 0; k < 8; k++) {
                xe[k] = fmaf(v[j], re[j * 8 + k], xe[k]);
                xo[k] = fmaf(v[j], ro[j * 8 + k], xo[k]);
            }
        float* pe = out + ((size_t)(128 * bt + c)) * 8;
        *(float4*)(pe + 0)   = make_float4(xe[0], xe[1], xe[2], xe[3]);
        *(float4*)(pe + 4)   = make_float4(xe[4], xe[5], xe[6], xe[7]);
        *(float4*)(pe + 512) = make_float4(xo[0], xo[1], xo[2], xo[3]);
        *(float4*)(pe + 516) = make_float4(xo[4], xo[5], xo[6], xo[7]);
    }
}

// ===========================================================================
// Host orchestration
// ===========================================================================
#define SYM(p, s) do { void* _t; cudaGetSymbolAddress(&_t, s); p = (decltype(p))_t; } while (0)

extern "C" void kernel_launch(void* const* d_in, const int* in_sizes, int n_in,
                              void* d_out, int out_size)
{
    const float* x        = (const float*)d_in[0];
    const float* lin_in_w = (const float*)d_in[1];
    const float* lin_in_b = (const float*)d_in[2];
    const float* lin_out_w= (const float*)d_in[3];
    const float* lin_out_b= (const float*)d_in[4];
    const float* t0_w     = (const float*)d_in[5];
    const float* t0_b     = (const float*)d_in[6];
    const float* wA_re    = (const float*)d_in[7];
    const float* wA_im    = (const float*)d_in[8];
    const float* wB_re    = (const float*)d_in[9];
    const float* wB_im    = (const float*)d_in[10];
    const float* wC_re    = (const float*)d_in[11];
    const float* wC_im    = (const float*)d_in[12];
    const float* ec_s     = (const float*)d_in[13];
    const float* ec_d     = (const float*)d_in[14];
    const float* rc_e     = (const float*)d_in[15];
    const float* rc_o     = (const float*)d_in[16];

    float *pz, *pd0, *ps0, *pd1, *ps1, *pUS0, *pUS1;
    float *prec1, *prec0, *pzfp, *pzf, *pmixp, *pmix;
    float *pbF2, *pbI2, *pbF1, *pbI1, *pbt32;
    SYM(pz, g_z); SYM(pd0, g_d0); SYM(ps0, g_s0);
    SYM(pd1, g_d1); SYM(ps1, g_s1);
    SYM(pUS0, g_US0); SYM(pUS1, g_US1);
    SYM(prec1, g_rec1); SYM(prec0, g_rec0);
    SYM(pzfp, g_zf_part); SYM(pzf, g_zf);
    SYM(pmixp, g_mixp); SYM(pmix, g_mix);
    SYM(pbF2, g_bF2048); SYM(pbI2, g_bI2048); SYM(pbF1, g_bF1024); SYM(pbI1, g_bI1024);
    SYM(pbt32, g_bt32);

    const int ZFCOUNT  = 32 * 512 * 64;
    const int MIXCOUNT = 32 * 512 * 64;

    // 0) basis tables
    basis_kernel<<<512, 256>>>();

    // 1) lin_in via tf32 mma
    wgt_tf32<<<dim3(16, 16), dim3(32, 8)>>>(lin_in_w, pbt32);
    gemm_tf32<<<dim3(4, 256), 256>>>(x, pbt32, lin_in_b, pz);

    // 2) both encodes
    encode_kernel<<<(8 * 2048 * 32) / 256, 256>>>(pz, ec_d, ec_s, pd0, ps0, 2048);
    encode_kernel<<<(8 * 1024 * 32) / 256, 256>>>(ps0, ec_d, ec_s, pd1, ps1, 1024);

    // 3) forward DFTs, both levels, one launch
    dftfwd_kernel<<<dim3(4, 8, 32), 256>>>(pd0, ps0, pd1, ps1, pbF2, pbF1, pzfp);
    reduce_parts<<<(ZFCOUNT + 255) / 256, 256>>>(pzfp, pzf, ZFCOUNT, 8);

    // 4) modemix split U/S, i-split 8, 2 o per warp, vectorized z smem
    modemix_U<<<dim3(32, 8), 256>>>(pzf, wA_re, wA_im, wB_re, wB_im, pmixp);
    modemix_S<<<dim3(32, 8), 256>>>(pzf, wC_re, wC_im, pmixp);
    reduce_parts<<<(MIXCOUNT + 255) / 256, 256>>>(pmixp, pmix, MIXCOUNT, 8);

    // 5) inverse DFTs via tf32 mma (z-batched)
    invdft_tf32<<<dim3(4, 16, 16), 256>>>(pbI2, pmix, pUS0, 2048);
    invdft_tf32<<<dim3(4, 8, 16), 256>>>(pbI1, pmix + 16ull * 512 * 64, pUS1, 1024);

    // 6) reconstruction (t0 fused into level-1 recon)
    recon_t0_kernel<<<(8 * 1024 * 32) / 256, 256>>>(
        ps1, pUS1 + 8ull * 1024 * 512, pUS1, rc_e, rc_o, t0_w, t0_b, prec1, 1024);
    recon_kernel<<<(8 * 2048 * 32) / 256, 256>>>(
        prec1, pUS0 + 8ull * 2048 * 512, pUS0, rc_e, rc_o, prec0, 2048);

    // 7) lin_out via tf32 mma -> d_out
    wgt_tf32<<<dim3(16, 16), dim3(32, 8)>>>(lin_out_w, pbt32);
    gemm_tf32<<<dim3(4, 256), 256>>>(prec0, pbt32, lin_out_b, (float*)d_out);

    (void)in_sizes; (void)n_in; (void)out_size;
}

// round 15
// speedup vs baseline: 1.3015x; 1.0649x over previous
#include <cuda_runtime.h>
#include <cuda_bf16.h>
#include <math.h>
#include <stdint.h>

// Problem constants: B=8, T=4096, H=8, D=64, CK=512, K=8, C=64, MODES=32, L=2

#define DEVBUF __device__ __align__(256)
DEVBUF float g_z   [8ull*4096*512];
DEVBUF float g_d0  [8ull*2048*512];
DEVBUF float g_s0  [8ull*2048*512];
DEVBUF float g_d1  [8ull*1024*512];
DEVBUF float g_s1  [8ull*1024*512];
DEVBUF float g_US0 [16ull*2048*512];
DEVBUF float g_US1 [16ull*1024*512];
DEVBUF float g_rec1[8ull*2048*512];
DEVBUF float g_rec0[8ull*4096*512];
DEVBUF float g_zf_part[8ull*32*512*64];
DEVBUF float g_zf     [32ull*512*64];
DEVBUF float g_mixp[8ull*32*512*64];
DEVBUF float g_mix [32ull*512*64];
DEVBUF float g_bI2048[2048*64];        // tf32-prerounded
DEVBUF float g_bI1024[1024*64];        // tf32-prerounded
DEVBUF float g_bFT2048[64*2048];       // transposed fwd basis, tf32-prerounded
DEVBUF float g_bFT1024[64*1024];
DEVBUF float g_bt32[512ull*512];

// ===========================================================================
// Helpers
// ===========================================================================
__device__ __forceinline__ uint32_t smem_u32(const void* p) {
    uint32_t a;
    asm("{ .reg .u64 t; cvta.to.shared.u64 t, %1; cvt.u32.u64 %0, t; }" : "=r"(a) : "l"(p));
    return a;
}
__device__ __forceinline__ void cp16(uint32_t smaddr, const void* g) {
    asm volatile("cp.async.cg.shared.global [%0], [%1], 16;" :: "r"(smaddr), "l"(g));
}
#define CP_COMMIT() asm volatile("cp.async.commit_group;" ::: "memory")
#define CP_WAIT2()  asm volatile("cp.async.wait_group 2;" ::: "memory")

__device__ __forceinline__ void ldsm4(uint32_t* r, uint32_t a) {
    asm volatile("ldmatrix.sync.aligned.m8n8.x4.shared.b16 {%0,%1,%2,%3}, [%4];"
        : "=r"(r[0]), "=r"(r[1]), "=r"(r[2]), "=r"(r[3]) : "r"(a));
}
__device__ __forceinline__ void ldsm2(uint32_t* r, uint32_t a) {
    asm volatile("ldmatrix.sync.aligned.m8n8.x2.shared.b16 {%0,%1}, [%2];"
        : "=r"(r[0]), "=r"(r[1]) : "r"(a));
}
__device__ __forceinline__ void mma_tf32(float* c, const uint32_t* a, const uint32_t* b) {
    asm volatile("mma.sync.aligned.m16n8k8.row.col.f32.tf32.tf32.f32 "
        "{%0,%1,%2,%3}, {%4,%5,%6,%7}, {%8,%9}, {%0,%1,%2,%3};"
        : "+f"(c[0]), "+f"(c[1]), "+f"(c[2]), "+f"(c[3])
        : "r"(a[0]), "r"(a[1]), "r"(a[2]), "r"(a[3]), "r"(b[0]), "r"(b[1]));
}
__device__ __forceinline__ uint32_t cvt_tf32(uint32_t u) {
    uint32_t o;
    float f = __uint_as_float(u);
    asm("cvt.rna.tf32.f32 %0, %1;" : "=r"(o) : "f"(f));
    return o;
}

// ===========================================================================
// tf32 mma GEMM (proven): C[32768,512] = A[32768,512] @ W[512,512]+bias
// ===========================================================================
__global__ __launch_bounds__(256, 2) void gemm_tf32(
    const float* __restrict__ A, const float* __restrict__ Bt,
    const float* __restrict__ bias, float* __restrict__ C)
{
    __shared__ __align__(1024) float sA[3][128 * 16];
    __shared__ __align__(1024) float sB[3][128 * 16];

    const int tid  = threadIdx.x;
    const int wid  = tid >> 5;
    const int lane = tid & 31;
    const int m0 = blockIdx.y * 128;
    const int n0 = blockIdx.x * 128;
    const int wm = (wid >> 1) * 32;
    const int wn = (wid & 1) * 64;

    const uint32_t sA0 = smem_u32(sA);
    const uint32_t sB0 = smem_u32(sB);

    const int r0 = (tid + 0)   >> 2, c0 = (tid + 0)   & 3;
    const int r1 = (tid + 256) >> 2, c1 = (tid + 256) & 3;
    const uint32_t so0 = (uint32_t)(r0 * 64 + ((c0 ^ ((r0 >> 1) & 3)) * 16));
    const uint32_t so1 = (uint32_t)(r1 * 64 + ((c1 ^ ((r1 >> 1) & 3)) * 16));

    auto load_chunk = [&](int it, int s) {
        const int kb = it * 16;
        cp16(sA0 + s * 8192 + so0, A + (size_t)(m0 + r0) * 512 + kb + c0 * 4);
        cp16(sA0 + s * 8192 + so1, A + (size_t)(m0 + r1) * 512 + kb + c1 * 4);
        cp16(sB0 + s * 8192 + so0, Bt + (size_t)(n0 + r0) * 512 + kb + c0 * 4);
        cp16(sB0 + s * 8192 + so1, Bt + (size_t)(n0 + r1) * 512 + kb + c1 * 4);
        CP_COMMIT();
    };

    float acc[2][8][4];
#pragma unroll
    for (int i = 0; i < 2; i++)
#pragma unroll
        for (int j = 0; j < 8; j++)
#pragma unroll
            for (int k = 0; k < 4; k++) acc[i][j][k] = 0.f;

    const int la = lane & 15;
    const int ka = lane >> 4;
    const int lb = lane & 7;
    const int kb8 = (lane >> 3) & 1;

    load_chunk(0, 0);
    load_chunk(1, 1);

    const int NC = 32;
    for (int it = 0; it < NC; it++) {
        const int s = it % 3;
        if (it + 2 < NC) load_chunk(it + 2, (it + 2) % 3);
        else CP_COMMIT();
        CP_WAIT2();
        __syncthreads();

#pragma unroll
        for (int k8 = 0; k8 < 2; k8++) {
            uint32_t afr[2][4];
#pragma unroll
            for (int tm = 0; tm < 2; tm++) {
                int row = wm + tm * 16 + la;
                int k4 = k8 * 2 + ka;
                uint32_t addr = sA0 + s * 8192 + (uint32_t)(row * 64 + ((k4 ^ ((row >> 1) & 3)) * 16));
                ldsm4(afr[tm], addr);
#pragma unroll
                for (int q = 0; q < 4; q++) afr[tm][q] = cvt_tf32(afr[tm][q]);
            }
            uint32_t bfr[8][2];
#pragma unroll
            for (int n8 = 0; n8 < 8; n8++) {
                int row = wn + n8 * 8 + lb;
                int k4 = k8 * 2 + kb8;
                uint32_t addr = sB0 + s * 8192 + (uint32_t)(row * 64 + ((k4 ^ ((row >> 1) & 3)) * 16));
                ldsm2(bfr[n8], addr);
            }
#pragma unroll
            for (int tm = 0; tm < 2; tm++)
#pragma unroll
                for (int n8 = 0; n8 < 8; n8++)
                    mma_tf32(acc[tm][n8], afr[tm], bfr[n8]);
        }
        __syncthreads();
    }

    const int er = lane >> 2;
    const int ec = (lane & 3) * 2;
#pragma unroll
    for (int tm = 0; tm < 2; tm++) {
        const int m = m0 + wm + tm * 16 + er;
#pragma unroll
        for (int n8 = 0; n8 < 8; n8++) {
            const int n = n0 + wn + n8 * 8 + ec;
            const float b0 = bias[n], b1 = bias[n + 1];
            float2 v0 = make_float2(acc[tm][n8][0] + b0, acc[tm][n8][1] + b1);
            float2 v1 = make_float2(acc[tm][n8][2] + b0, acc[tm][n8][3] + b1);
            *(float2*)&C[(size_t)m * 512 + n]       = v0;
            *(float2*)&C[(size_t)(m + 8) * 512 + n] = v1;
        }
    }
}

__global__ void wgt_tf32(const float* __restrict__ W, float* __restrict__ Bt) {
    __shared__ float t[32][33];
    const int n0 = blockIdx.x * 32, k0 = blockIdx.y * 32;
    for (int i = threadIdx.y; i < 32; i += 8)
        t[i][threadIdx.x] = W[(size_t)(k0 + i) * 512 + n0 + threadIdx.x];
    __syncthreads();
    for (int i = threadIdx.y; i < 32; i += 8) {
        uint32_t v = cvt_tf32(__float_as_uint(t[threadIdx.x][i]));
        Bt[(size_t)(n0 + i) * 512 + k0 + threadIdx.x] = __uint_as_float(v);
    }
}

// ===========================================================================
// Inverse-DFT via tf32 mma: C[z][t][i] = bI[t][m] @ mixT[z][i][m]
// ===========================================================================
__global__ __launch_bounds__(256, 2) void invdft_tf32(
    const float* __restrict__ Abi, const float* __restrict__ Bm,
    float* __restrict__ C, int n2)
{
    __shared__ __align__(1024) float sA[3][128 * 16];
    __shared__ __align__(1024) float sB[3][128 * 16];

    const int tid  = threadIdx.x;
    const int wid  = tid >> 5;
    const int lane = tid & 31;
    const int m0 = blockIdx.y * 128;
    const int n0 = blockIdx.x * 128;
    const int z  = blockIdx.z;
    Bm += (size_t)z * 512 * 64;
    C  += (size_t)z * n2 * 512;
    const int wm = (wid >> 1) * 32;
    const int wn = (wid & 1) * 64;

    const uint32_t sA0 = smem_u32(sA);
    const uint32_t sB0 = smem_u32(sB);

    const int r0 = tid >> 2, c0 = tid & 3;
    const int r1 = r0 + 64;
    const uint32_t so0 = (uint32_t)(r0 * 64 + ((c0 ^ ((r0 >> 1) & 3)) * 16));
    const uint32_t so1 = (uint32_t)(r1 * 64 + ((c0 ^ ((r1 >> 1) & 3)) * 16));

    auto load_chunk = [&](int it, int s) {
        const int kb = it * 16;
        cp16(sA0 + s * 8192 + so0, Abi + (size_t)(m0 + r0) * 64 + kb + c0 * 4);
        cp16(sA0 + s * 8192 + so1, Abi + (size_t)(m0 + r1) * 64 + kb + c0 * 4);
        cp16(sB0 + s * 8192 + so0, Bm + (size_t)(n0 + r0) * 64 + kb + c0 * 4);
        cp16(sB0 + s * 8192 + so1, Bm + (size_t)(n0 + r1) * 64 + kb + c0 * 4);
        CP_COMMIT();
    };

    float acc[2][8][4];
#pragma unroll
    for (int i = 0; i < 2; i++)
#pragma unroll
        for (int j = 0; j < 8; j++)
#pragma unroll
            for (int k = 0; k < 4; k++) acc[i][j][k] = 0.f;

    const int la = lane & 15;
    const int ka = lane >> 4;
    const int b_r = wn + (lane & 7) + ((lane & 16) ? 8 : 0);
    const int b_u = (lane >> 3) & 1;

    load_chunk(0, 0);
    load_chunk(1, 1);

    const int NC = 4;
    for (int it = 0; it < NC; it++) {
        const int s = it % 3;
        if (it + 2 < NC) load_chunk(it + 2, (it + 2) % 3);
        else CP_COMMIT();
        CP_WAIT2();
        __syncthreads();

#pragma unroll
        for (int k8 = 0; k8 < 2; k8++) {
            uint32_t afr[2][4];
#pragma unroll
            for (int tm = 0; tm < 2; tm++) {
                int row = wm + tm * 16 + la;
                int k4 = k8 * 2 + ka;
                uint32_t addr = sA0 + s * 8192 + (uint32_t)(row * 64 + ((k4 ^ ((row >> 1) & 3)) * 16));
                ldsm4(afr[tm], addr);
            }
            uint32_t bfr[4][4];
#pragma unroll
            for (int p = 0; p < 4; p++) {
                int row = b_r + p * 16;
                int k4 = k8 * 2 + b_u;
                uint32_t addr = sB0 + s * 8192 + (uint32_t)(row * 64 + ((k4 ^ ((row >> 1) & 3)) * 16));
                ldsm4(bfr[p], addr);
#pragma unroll
                for (int q = 0; q < 4; q++) bfr[p][q] = cvt_tf32(bfr[p][q]);
            }
#pragma unroll
            for (int tm = 0; tm < 2; tm++)
#pragma unroll
                for (int p = 0; p < 4; p++) {
                    mma_tf32(acc[tm][p * 2 + 0], afr[tm], &bfr[p][0]);
                    mma_tf32(acc[tm][p * 2 + 1], afr[tm], &bfr[p][2]);
                }
        }
        __syncthreads();
    }

    const int er = lane >> 2;
    const int ec = (lane & 3) * 2;
#pragma unroll
    for (int tm = 0; tm < 2; tm++) {
        const int m = m0 + wm + tm * 16 + er;
#pragma unroll
        for (int n8 = 0; n8 < 8; n8++) {
            const int n = n0 + wn + n8 * 8 + ec;
            *(float2*)&C[(size_t)m * 512 + n]       = make_float2(acc[tm][n8][0], acc[tm][n8][1]);
            *(float2*)&C[(size_t)(m + 8) * 512 + n] = make_float2(acc[tm][n8][2], acc[tm][n8][3]);
        }
    }
}

// ===========================================================================
// Forward truncated DFT via tf32 mma:
//   C[m][i] = sum_t bFT[m][t] * z[t][i]    (per slot g; split-K = 2)
// A = bFT (pre-rounded tf32, k-contiguous, ldsm4). B = z chunk staged as-is
// [t][i] (pad-136 rows), fragments via 2 conflict-free scalar LDS.
// Grid (4 i-tiles, 2 ksplit, 32 slots), 256 thr, warp tile 16m x 64i.
// ===========================================================================
__global__ __launch_bounds__(256, 2) void dftfwd_tf32(
    const float* __restrict__ zd0, const float* __restrict__ zs0,
    const float* __restrict__ zd1, const float* __restrict__ zs1,
    const float* __restrict__ bFT0, const float* __restrict__ bFT1,
    float* __restrict__ out_part)
{
    __shared__ __align__(1024) float sA[3][64 * 16];
    __shared__ __align__(1024) float sB[3][16 * 136];

    const int tid  = threadIdx.x;
    const int wid  = tid >> 5;
    const int lane = tid & 31;
    const int g = blockIdx.z;
    const float* z;
    const float* bFT;
    int n;
    if (g < 16) { z = (g < 8) ? zd0 : zs0; bFT = bFT0; n = 2048; }
    else        { z = (g < 24) ? zd1 : zs1; bFT = bFT1; n = 1024; }
    z += (size_t)(g & 7) * n * 512;
    const int kchunk = n >> 1;
    const int NC = kchunk >> 4;
    const int i0 = blockIdx.x * 128;
    const int tbase = blockIdx.y * kchunk;

    const int wm = (wid >> 1) * 16;
    const int wn = (wid & 1) * 64;

    const uint32_t sAb = smem_u32(sA);
    const uint32_t sBb = smem_u32(sB);

    const int ar = tid >> 2, ac = tid & 3;
    const uint32_t aso = (uint32_t)(ar * 64 + ((ac ^ ((ar >> 1) & 3)) * 16));
    const int btr = tid >> 4;
    const int bfc = (tid & 15) * 2;

    auto load_chunk = [&](int c, int s) {
        const int kb = tbase + c * 16;
        cp16(sAb + s * 4096 + aso, bFT + (size_t)ar * n + kb + ac * 4);
        uint32_t bd = sBb + s * 8704 + (uint32_t)(btr * 544 + bfc * 16);
        const float* bs = z + (size_t)(kb + btr) * 512 + i0 + bfc * 4;
        cp16(bd, bs);
        cp16(bd + 16, bs + 4);
        CP_COMMIT();
    };

    float acc[8][4];
#pragma unroll
    for (int j = 0; j < 8; j++)
#pragma unroll
        for (int k = 0; k < 4; k++) acc[j][k] = 0.f;

    const int la = lane & 15;
    const int ka = lane >> 4;
    const int bt_k = lane & 3;     // B frag k within quad
    const int bt_n = lane >> 2;    // B frag n within 8

    load_chunk(0, 0);
    load_chunk(1, 1);

    for (int it = 0; it < NC; it++) {
        const int s = it % 3;
        if (it + 2 < NC) load_chunk(it + 2, (it + 2) % 3);
        else CP_COMMIT();
        CP_WAIT2();
        __syncthreads();

        const float* zs = &sB[s][0];
#pragma unroll
        for (int k8 = 0; k8 < 2; k8++) {
            uint32_t afr[4];
            {
                int row = wm + la;
                int k4 = k8 * 2 + ka;
                uint32_t addr = sAb + s * 4096 + (uint32_t)(row * 64 + ((k4 ^ ((row >> 1) & 3)) * 16));
                ldsm4(afr, addr);
            }
            const int tl = k8 * 8 + bt_k;
#pragma unroll
            for (int n8 = 0; n8 < 8; n8++) {
                int ii = wn + n8 * 8 + bt_n;
                uint32_t b[2];
                b[0] = cvt_tf32(__float_as_uint(zs[tl * 136 + ii]));
                b[1] = cvt_tf32(__float_as_uint(zs[(tl + 4) * 136 + ii]));
                mma_tf32(acc[n8], afr, b);
            }
        }
        __syncthreads();
    }

    const int er = lane >> 2;
    const int ec = (lane & 3) * 2;
    const size_t sbase = ((size_t)blockIdx.y * 32 + g) * 512;
#pragma unroll
    for (int n8 = 0; n8 < 8; n8++) {
        int ii = i0 + wn + n8 * 8 + ec;
        int m = wm + er;
        out_part[(sbase + ii) * 64 + m]           = acc[n8][0];
        out_part[(sbase + ii + 1) * 64 + m]       = acc[n8][1];
        out_part[(sbase + ii) * 64 + m + 8]       = acc[n8][2];
        out_part[(sbase + ii + 1) * 64 + m + 8]   = acc[n8][3];
    }
}

// ===========================================================================
// Basis tables: bI (tf32) and transposed bFT (tf32)
// ===========================================================================
__device__ __forceinline__ void fill_tables(float* bFT, float* bI, int t, int m, int n) {
    int x = (m < 32) ? m : (m - 32);
    long r = ((long)t * (long)x) % (long)n;
    double ang = 6.283185307179586476925286766559 * (double)r / (double)n;
    double c = cos(ang), s = sin(ang);
    float vf = (m < 32) ? (float)c : (float)s;
    bFT[(size_t)m * n + t] = __uint_as_float(cvt_tf32(__float_as_uint(vf)));
    float vi;
    if (m == 0)          vi = 1.0f / (float)n;
    else if (m < 32)     vi = (float)(2.0 * c / (double)n);
    else if (m == 32)    vi = 0.0f;
    else                 vi = (float)(-2.0 * s / (double)n);
    bI[t*64 + m] = __uint_as_float(cvt_tf32(__float_as_uint(vi)));
}

__global__ __launch_bounds__(256) void basis_kernel() {
    int idx = blockIdx.x * 256 + threadIdx.x;
    if (idx < 2048*64) {
        int t = idx >> 6, m = idx & 63;
        fill_tables(g_bFT2048, g_bI2048, t, m, 2048);
    }
    if (idx < 1024*64) {
        int t = idx >> 6, m = idx & 63;
        fill_tables(g_bFT1024, g_bI1024, t, m, 1024);
    }
}

// ===========================================================================
// Encode: 2 channels per thread
// ===========================================================================
__global__ __launch_bounds__(256) void encode_kernel(
    const float* __restrict__ cur, const float* __restrict__ ec_d,
    const float* __restrict__ ec_s, float* __restrict__ dco,
    float* __restrict__ sco, int n2)
{
    __shared__ float ed[128], es[128];
    if (threadIdx.x < 128) { ed[threadIdx.x] = ec_d[threadIdx.x]; es[threadIdx.x] = ec_s[threadIdx.x]; }
    __syncthreads();
    int idx = blockIdx.x * 256 + threadIdx.x;
    int total = 8 * n2 * 32;
    if (idx >= total) return;
    int cp = idx & 31;
    int bt = idx >> 5;
    const float* pe = cur + ((size_t)(128 * bt) + cp * 2) * 8;

    float4 ve[2][4];
#pragma unroll
    for (int cc = 0; cc < 2; cc++) {
        const float* p = pe + cc * 8;
        ve[cc][0] = *(const float4*)(p + 0);
        ve[cc][1] = *(const float4*)(p + 4);
        ve[cc][2] = *(const float4*)(p + 512);
        ve[cc][3] = *(const float4*)(p + 516);
    }
#pragma unroll
    for (int cc = 0; cc < 2; cc++) {
        float xa[16];
        xa[0]=ve[cc][0].x; xa[1]=ve[cc][0].y; xa[2]=ve[cc][0].z; xa[3]=ve[cc][0].w;
        xa[4]=ve[cc][1].x; xa[5]=ve[cc][1].y; xa[6]=ve[cc][1].z; xa[7]=ve[cc][1].w;
        xa[8]=ve[cc][2].x; xa[9]=ve[cc][2].y; xa[10]=ve[cc][2].z; xa[11]=ve[cc][2].w;
        xa[12]=ve[cc][3].x; xa[13]=ve[cc][3].y; xa[14]=ve[cc][3].z; xa[15]=ve[cc][3].w;
        float d[8] = {0,0,0,0,0,0,0,0}, s[8] = {0,0,0,0,0,0,0,0};
#pragma unroll
        for (int j = 0; j < 16; j++)
#pragma unroll
            for (int k = 0; k < 8; k++) {
                d[k] = fmaf(xa[j], ed[j * 8 + k], d[k]);
                s[k] = fmaf(xa[j], es[j * 8 + k], s[k]);
            }
        size_t ob = ((size_t)bt * 64 + cp * 2 + cc) * 8;
        *(float4*)&dco[ob]     = make_float4(d[0], d[1], d[2], d[3]);
        *(float4*)&dco[ob + 4] = make_float4(d[4], d[5], d[6], d[7]);
        *(float4*)&sco[ob]     = make_float4(s[0], s[1], s[2], s[3]);
        *(float4*)&sco[ob + 4] = make_float4(s[4], s[5], s[6], s[7]);
    }
}

__global__ __launch_bounds__(256) void reduce_parts(
    const float* __restrict__ part, float* __restrict__ out, int count, int nparts)
{
    int e = blockIdx.x * 256 + threadIdx.x;
    if (e >= count) return;
    float s = 0.f;
    for (int p = 0; p < nparts; p++) s += part[(size_t)p * count + e];
    out[e] = s;
}

// ===========================================================================
// Mode mixing SPLIT U/S, i-split 8, 2 o per warp, vectorized z smem
// ===========================================================================
__global__ __launch_bounds__(256) void modemix_U(
    const float* __restrict__ zf,
    const float* __restrict__ waR, const float* __restrict__ waI,
    const float* __restrict__ wbR, const float* __restrict__ wbI,
    float* __restrict__ out_part)
{
    __shared__ float4 zS[2][8][8][32];
    const int x = threadIdx.x & 31;
    const int q = threadIdx.x >> 5;
    const int o0 = blockIdx.x * 16 + q * 2;
    const int i0 = blockIdx.y * 64;

    float uR[2][16], uI[2][16];
#pragma unroll
    for (int oo = 0; oo < 2; oo++)
#pragma unroll
        for (int b = 0; b < 16; b++) { uR[oo][b]=0.f; uI[oo][b]=0.f; }

    for (int ic = 0; ic < 64; ic += 8) {
        __syncthreads();
        for (int e = threadIdx.x; e < 4096; e += 256) {
            int lev = e >> 11, r = e & 2047;
            int b = r >> 8, rr = r & 255, ii = rr >> 5, xx = rr & 31;
            size_t gidx = ((size_t)b * 512 + (i0 + ic + ii)) * 64;
            size_t lbase = (size_t)lev * 16 * 512 * 64;
            size_t sofs  = 8ull * 512 * 64;
            zS[lev][b][ii][xx] = make_float4(
                zf[lbase + gidx + xx],        zf[lbase + gidx + 32 + xx],
                zf[lbase + sofs + gidx + xx], zf[lbase + sofs + gidx + 32 + xx]);
        }
        __syncthreads();
#pragma unroll 2
        for (int ii = 0; ii < 8; ii++) {
            int i = i0 + ic + ii;
            float war[2], wai[2], wbr[2], wbi[2];
#pragma unroll
            for (int oo = 0; oo < 2; oo++) {
                size_t wbase = ((size_t)i * 512 + o0 + oo) * 32 + x;
                war[oo] = waR[wbase]; wai[oo] = waI[wbase];
                wbr[oo] = wbR[wbase]; wbi[oo] = wbI[wbase];
            }
#pragma unroll
            for (int lev = 0; lev < 2; lev++)
#pragma unroll
            for (int b = 0; b < 8; b++) {
                int bb = lev * 8 + b;
                float4 zv = zS[lev][b][ii][x];
                float zr = zv.x, zi = -zv.y, sr = zv.z, si = -zv.w;
#pragma unroll
                for (int oo = 0; oo < 2; oo++) {
                    uR[oo][bb] = fmaf(zr, war[oo], uR[oo][bb]); uR[oo][bb] = fmaf(-zi, wai[oo], uR[oo][bb]);
                    uR[oo][bb] = fmaf(sr, wbr[oo], uR[oo][bb]); uR[oo][bb] = fmaf(-si, wbi[oo], uR[oo][bb]);
                    uI[oo][bb] = fmaf(zr, wai[oo], uI[oo][bb]); uI[oo][bb] = fmaf(zi, war[oo], uI[oo][bb]);
                    uI[oo][bb] = fmaf(sr, wbi[oo], uI[oo][bb]); uI[oo][bb] = fmaf(si, wbr[oo], uI[oo][bb]);
                }
            }
        }
    }
#pragma unroll
    for (int bb = 0; bb < 16; bb++) {
        int lev = bb >> 3, b = bb & 7;
        size_t slotU = (size_t)blockIdx.y * 32 + lev * 16 + b;
#pragma unroll
        for (int oo = 0; oo < 2; oo++) {
            out_part[(slotU * 512 + o0 + oo) * 64 + x]      = uR[oo][bb];
            out_part[(slotU * 512 + o0 + oo) * 64 + 32 + x] = uI[oo][bb];
        }
    }
}

__global__ __launch_bounds__(256) void modemix_S(
    const float* __restrict__ zf,
    const float* __restrict__ wcR, const float* __restrict__ wcI,
    float* __restrict__ out_part)
{
    __shared__ float2 zS[2][8][8][32];
    const int x = threadIdx.x & 31;
    const int q = threadIdx.x >> 5;
    const int o0 = blockIdx.x * 16 + q * 2;
    const int i0 = blockIdx.y * 64;

    float sR[2][16], sI[2][16];
#pragma unroll
    for (int oo = 0; oo < 2; oo++)
#pragma unroll
        for (int b = 0; b < 16; b++) { sR[oo][b]=0.f; sI[oo][b]=0.f; }

    for (int ic = 0; ic < 64; ic += 8) {
        __syncthreads();
        for (int e = threadIdx.x; e < 4096; e += 256) {
            int lev = e >> 11, r = e & 2047;
            int b = r >> 8, rr = r & 255, ii = rr >> 5, xx = rr & 31;
            size_t gidx = ((size_t)b * 512 + (i0 + ic + ii)) * 64;
            size_t lbase = (size_t)lev * 16 * 512 * 64;
            zS[lev][b][ii][xx] = make_float2(zf[lbase + gidx + xx], zf[lbase + gidx + 32 + xx]);
        }
        __syncthreads();
#pragma unroll 2
        for (int ii = 0; ii < 8; ii++) {
            int i = i0 + ic + ii;
            float wcr[2], wci[2];
#pragma unroll
            for (int oo = 0; oo < 2; oo++) {
                size_t wbase = ((size_t)i * 512 + o0 + oo) * 32 + x;
                wcr[oo] = wcR[wbase]; wci[oo] = wcI[wbase];
            }
#pragma unroll
            for (int lev = 0; lev < 2; lev++)
#pragma unroll
            for (int b = 0; b < 8; b++) {
                int bb = lev * 8 + b;
                float2 zv = zS[lev][b][ii][x];
                float zr = zv.x, zi = -zv.y;
#pragma unroll
                for (int oo = 0; oo < 2; oo++) {
                    sR[oo][bb] = fmaf(zr, wcr[oo], sR[oo][bb]); sR[oo][bb] = fmaf(-zi, wci[oo], sR[oo][bb]);
                    sI[oo][bb] = fmaf(zr, wci[oo], sI[oo][bb]); sI[oo][bb] = fmaf(zi, wcr[oo], sI[oo][bb]);
                }
            }
        }
    }
#pragma unroll
    for (int bb = 0; bb < 16; bb++) {
        int lev = bb >> 3, b = bb & 7;
        size_t slotS = (size_t)blockIdx.y * 32 + lev * 16 + 8 + b;
#pragma unroll
        for (int oo = 0; oo < 2; oo++) {
            out_part[(slotS * 512 + o0 + oo) * 64 + x]      = sR[oo][bb];
            out_part[(slotS * 512 + o0 + oo) * 64 + 32 + x] = sI[oo][bb];
        }
    }
}

// ===========================================================================
// Recon with fused t0 (level 1), 2 channels/thread
// ===========================================================================
__global__ __launch_bounds__(256) void recon_t0_kernel(
    const float* __restrict__ cur, const float* __restrict__ us,
    const float* __restrict__ ud, const float* __restrict__ rc_e,
    const float* __restrict__ rc_o, const float* __restrict__ t0w,
    const float* __restrict__ t0b, float* __restrict__ out, int n2)
{
    __shared__ float re[128], ro[128], w[64], bb[8];
    if (threadIdx.x < 128) { re[threadIdx.x] = rc_e[threadIdx.x]; ro[threadIdx.x] = rc_o[threadIdx.x]; }
    if (threadIdx.x < 64)  w[threadIdx.x] = t0w[threadIdx.x];
    if (threadIdx.x >= 64 && threadIdx.x < 72) bb[threadIdx.x - 64] = t0b[threadIdx.x - 64];
    __syncthreads();
    int idx = blockIdx.x * 256 + threadIdx.x;
    int total = 8 * n2 * 32;
    if (idx >= total) return;
    int cp = idx & 31;
    int bt = idx >> 5;

    float4 vc[2][2], vu[2][2], vd[2][2];
#pragma unroll
    for (int cc = 0; cc < 2; cc++) {
        size_t base = ((size_t)bt * 64 + cp * 2 + cc) * 8;
        vc[cc][0] = *(const float4*)(cur + base); vc[cc][1] = *(const float4*)(cur + base + 4);
        vu[cc][0] = *(const float4*)(us + base);  vu[cc][1] = *(const float4*)(us + base + 4);
        vd[cc][0] = *(const float4*)(ud + base);  vd[cc][1] = *(const float4*)(ud + base + 4);
    }
#pragma unroll
    for (int cc = 0; cc < 2; cc++) {
        int c = cp * 2 + cc;
        float sv[8] = {vc[cc][0].x,vc[cc][0].y,vc[cc][0].z,vc[cc][0].w,
                       vc[cc][1].x,vc[cc][1].y,vc[cc][1].z,vc[cc][1].w};
        float uu[8] = {vu[cc][0].x,vu[cc][0].y,vu[cc][0].z,vu[cc][0].w,
                       vu[cc][1].x,vu[cc][1].y,vu[cc][1].z,vu[cc][1].w};
        float v[16];
        v[8]=vd[cc][0].x; v[9]=vd[cc][0].y; v[10]=vd[cc][0].z; v[11]=vd[cc][0].w;
        v[12]=vd[cc][1].x; v[13]=vd[cc][1].y; v[14]=vd[cc][1].z; v[15]=vd[cc][1].w;
#pragma unroll
        for (int k = 0; k < 8; k++) {
            float t = bb[k];
#pragma unroll
            for (int j = 0; j < 8; j++) t = fmaf(sv[j], w[j * 8 + k], t);
            v[k] = t + uu[k];
        }
        float xe[8] = {0,0,0,0,0,0,0,0}, xo[8] = {0,0,0,0,0,0,0,0};
#pragma unroll
        for (int j = 0; j < 16; j++)
#pragma unroll
            for (int k = 0; k < 8; k++) {
                xe[k] = fmaf(v[j], re[j * 8 + k], xe[k]);
                xo[k] = fmaf(v[j], ro[j * 8 + k], xo[k]);
            }
        float* pe = out + ((size_t)(128 * bt + c)) * 8;
        *(float4*)(pe + 0)   = make_float4(xe[0], xe[1], xe[2], xe[3]);
        *(float4*)(pe + 4)   = make_float4(xe[4], xe[5], xe[6], xe[7]);
        *(float4*)(pe + 512) = make_float4(xo[0], xo[1], xo[2], xo[3]);
        *(float4*)(pe + 516) = make_float4(xo[4], xo[5], xo[6], xo[7]);
    }
}

__global__ __launch_bounds__(256) void recon_kernel(
    const float* __restrict__ cur, const float* __restrict__ us,
    const float* __restrict__ ud, const float* __restrict__ rc_e,
    const float* __restrict__ rc_o, float* __restrict__ out, int n2)
{
    __shared__ float re[128], ro[128];
    if (threadIdx.x < 128) { re[threadIdx.x] = rc_e[threadIdx.x]; ro[threadIdx.x] = rc_o[threadIdx.x]; }
    __syncthreads();
    int idx = blockIdx.x * 256 + threadIdx.x;
    int total = 8 * n2 * 32;
    if (idx >= total) return;
    int cp = idx & 31;
    int bt = idx >> 5;

    float4 vc[2][2], vu[2][2], vd[2][2];
#pragma unroll
    for (int cc = 0; cc < 2; cc++) {
        size_t base = ((size_t)bt * 64 + cp * 2 + cc) * 8;
        vc[cc][0] = *(const float4*)(cur + base); vc[cc][1] = *(const float4*)(cur + base + 4);
        vu[cc][0] = *(const float4*)(us + base);  vu[cc][1] = *(const float4*)(us + base + 4);
        vd[cc][0] = *(const float4*)(ud + base);  vd[cc][1] = *(const float4*)(ud + base + 4);
    }
#pragma unroll
    for (int cc = 0; cc < 2; cc++) {
        int c = cp * 2 + cc;
        float v[16];
        v[0]=vc[cc][0].x+vu[cc][0].x; v[1]=vc[cc][0].y+vu[cc][0].y;
        v[2]=vc[cc][0].z+vu[cc][0].z; v[3]=vc[cc][0].w+vu[cc][0].w;
        v[4]=vc[cc][1].x+vu[cc][1].x; v[5]=vc[cc][1].y+vu[cc][1].y;
        v[6]=vc[cc][1].z+vu[cc][1].z; v[7]=vc[cc][1].w+vu[cc][1].w;
        v[8]=vd[cc][0].x; v[9]=vd[cc][0].y; v[10]=vd[cc][0].z; v[11]=vd[cc][0].w;
        v[12]=vd[cc][1].x; v[13]=vd[cc][1].y; v[14]=vd[cc][1].z; v[15]=vd[cc][1].w;
        float xe[8] = {0,0,0,0,0,0,0,0}, xo[8] = {0,0,0,0,0,0,0,0};
#pragma unroll
        for (int j = 0; j < 16; j++)
#pragma unroll
            for (int k = 0; k < 8; k++) {
                xe[k] = fmaf(v[j], re[j * 8 + k], xe[k]);
                xo[k] = fmaf(v[j], ro[j * 8 + k], xo[k]);
            }
        float* pe = out + ((size_t)(128 * bt + c)) * 8;
        *(float4*)(pe + 0)   = make_float4(xe[0], xe[1], xe[2], xe[3]);
        *(float4*)(pe + 4)   = make_float4(xe[4], xe[5], xe[6], xe[7]);
        *(float4*)(pe + 512) = make_float4(xo[0], xo[1], xo[2], xo[3]);
        *(float4*)(pe + 516) = make_float4(xo[4], xo[5], xo[6], xo[7]);
    }
}

// ===========================================================================
// Host orchestration
// ===========================================================================
#define SYM(p, s) do { void* _t; cudaGetSymbolAddress(&_t, s); p = (decltype(p))_t; } while (0)

extern "C" void kernel_launch(void* const* d_in, const int* in_sizes, int n_in,
                              void* d_out, int out_size)
{
    const float* x        = (const float*)d_in[0];
    const float* lin_in_w = (const float*)d_in[1];
    const float* lin_in_b = (const float*)d_in[2];
    const float* lin_out_w= (const float*)d_in[3];
    const float* lin_out_b= (const float*)d_in[4];
    const float* t0_w     = (const float*)d_in[5];
    const float* t0_b     = (const float*)d_in[6];
    const float* wA_re    = (const float*)d_in[7];
    const float* wA_im    = (const float*)d_in[8];
    const float* wB_re    = (const float*)d_in[9];
    const float* wB_im    = (const float*)d_in[10];
    const float* wC_re    = (const float*)d_in[11];
    const float* wC_im    = (const float*)d_in[12];
    const float* ec_s     = (const float*)d_in[13];
    const float* ec_d     = (const float*)d_in[14];
    const float* rc_e     = (const float*)d_in[15];
    const float* rc_o     = (const float*)d_in[16];

    float *pz, *pd0, *ps0, *pd1, *ps1, *pUS0, *pUS1;
    float *prec1, *prec0, *pzfp, *pzf, *pmixp, *pmix;
    float *pbI2, *pbI1, *pbFT2, *pbFT1, *pbt32;
    SYM(pz, g_z); SYM(pd0, g_d0); SYM(ps0, g_s0);
    SYM(pd1, g_d1); SYM(ps1, g_s1);
    SYM(pUS0, g_US0); SYM(pUS1, g_US1);
    SYM(prec1, g_rec1); SYM(prec0, g_rec0);
    SYM(pzfp, g_zf_part); SYM(pzf, g_zf);
    SYM(pmixp, g_mixp); SYM(pmix, g_mix);
    SYM(pbI2, g_bI2048); SYM(pbI1, g_bI1024);
    SYM(pbFT2, g_bFT2048); SYM(pbFT1, g_bFT1024);
    SYM(pbt32, g_bt32);

    const int ZFCOUNT  = 32 * 512 * 64;
    const int MIXCOUNT = 32 * 512 * 64;

    // 0) basis tables
    basis_kernel<<<512, 256>>>();

    // 1) lin_in via tf32 mma
    wgt_tf32<<<dim3(16, 16), dim3(32, 8)>>>(lin_in_w, pbt32);
    gemm_tf32<<<dim3(4, 256), 256>>>(x, pbt32, lin_in_b, pz);

    // 2) both encodes
    encode_kernel<<<(8 * 2048 * 32) / 256, 256>>>(pz, ec_d, ec_s, pd0, ps0, 2048);
    encode_kernel<<<(8 * 1024 * 32) / 256, 256>>>(ps0, ec_d, ec_s, pd1, ps1, 1024);

    // 3) forward DFTs via tf32 mma, both levels, ksplit 2
    dftfwd_tf32<<<dim3(4, 2, 32), 256>>>(pd0, ps0, pd1, ps1, pbFT2, pbFT1, pzfp);
    reduce_parts<<<(ZFCOUNT + 255) / 256, 256>>>(pzfp, pzf, ZFCOUNT, 2);

    // 4) modemix split U/S, i-split 8, 2 o per warp
    modemix_U<<<dim3(32, 8), 256>>>(pzf, wA_re, wA_im, wB_re, wB_im, pmixp);
    modemix_S<<<dim3(32, 8), 256>>>(pzf, wC_re, wC_im, pmixp);
    reduce_parts<<<(MIXCOUNT + 255) / 256, 256>>>(pmixp, pmix, MIXCOUNT, 8);

    // 5) inverse DFTs via tf32 mma (z-batched)
    invdft_tf32<<<dim3(4, 16, 16), 256>>>(pbI2, pmix, pUS0, 2048);
    invdft_tf32<<<dim3(4, 8, 16), 256>>>(pbI1, pmix + 16ull * 512 * 64, pUS1, 1024);

    // 6) reconstruction (t0 fused into level-1 recon)
    recon_t0_kernel<<<(8 * 1024 * 32) / 256, 256>>>(
        ps1, pUS1 + 8ull * 1024 * 512, pUS1, rc_e, rc_o, t0_w, t0_b, prec1, 1024);
    recon_kernel<<<(8 * 2048 * 32) / 256, 256>>>(
        prec1, pUS0 + 8ull * 2048 * 512, pUS0, rc_e, rc_o, prec0, 2048);

    // 7) lin_out via tf32 mma -> d_out
    wgt_tf32<<<dim3(16, 16), dim3(32, 8)>>>(lin_out_w, pbt32);
    gemm_tf32<<<dim3(4, 256), 256>>>(prec0, pbt32, lin_out_b, (float*)d_out);

    (void)in_sizes; (void)n_in; (void)out_size;
}